// round 1
// baseline (speedup 1.0000x reference)
#include <cuda_runtime.h>
#include <math.h>

#define BB 128
#define TT 512
#define DD 64
#define GW_STRIDE 2080
#define CACHE_D 24
#define HPAD 36

// Precomputed tables (setup kernel -> main kernel)
__device__ float d_A[4 * 32 * 32];   // A[c][j][k] = sum_i rnorm[c][i] * T[i][j][k]
__device__ float d_gr[4 * 64];       // gate_b[d] + sum_i gate_w[d][2048+i] * rnorm[c][i]

__global__ void setup_kernel(const float* __restrict__ emb,
                             const float* __restrict__ gate_w,
                             const float* __restrict__ gate_b,
                             const float* __restrict__ gp) {
    __shared__ float r[4][32];
    int t = threadIdx.x;           // 128 threads
    int c = t >> 5, i = t & 31;
    float v = emb[c * 32 + i];
    float s = v * v;
    #pragma unroll
    for (int off = 16; off; off >>= 1) s += __shfl_xor_sync(0xffffffffu, s, off);
    r[c][i] = v / (sqrtf(s) + 1e-8f);
    __syncthreads();

    // A table: 4096 entries
    for (int idx = t; idx < 4096; idx += 128) {
        int cc = idx >> 10, jk = idx & 1023;
        float acc = 0.f;
        #pragma unroll
        for (int ii = 0; ii < 32; ii++) acc += r[cc][ii] * gp[ii * 1024 + jk];
        d_A[idx] = acc;
    }
    // gate r-term table (+ bias folded)
    for (int idx = t; idx < 256; idx += 128) {
        int cc = idx >> 6, d = idx & 63;
        float acc = gate_b[d];
        #pragma unroll
        for (int ii = 0; ii < 32; ii++)
            acc += gate_w[d * GW_STRIDE + 2048 + ii] * r[cc][ii];
        d_gr[idx] = acc;
    }
}

__global__ void __launch_bounds__(256, 1)
versor_main_kernel(const int* __restrict__ x,
                   const float* __restrict__ gate_w,
                   const float* __restrict__ w1,
                   const float* __restrict__ b1,
                   const float* __restrict__ ln_g,
                   const float* __restrict__ ln_b,
                   const float* __restrict__ w2,
                   const float* __restrict__ b2,
                   float* __restrict__ out) {
    extern __shared__ float sm[];
    float* sW  = sm;                          // CACHE_D * 2048
    float* sH0 = sW + CACHE_D * 2048;         // 64 * HPAD
    float* sH1 = sH0 + DD * HPAD;             // 64 * HPAD
    float* sA  = sH1 + DD * HPAD;             // 4096
    float* sG  = sA + 4096;                   // 64
    float* sZ  = sG + 64;                     // 128

    const int tid  = threadIdx.x;
    const int lane = tid & 31;
    const int w    = tid >> 5;                // warp id 0..7
    const int b    = blockIdx.x;

    // ---- load cached gate_w rows (first 2048 cols of rows 0..23) ----
    for (int idx = tid; idx < CACHE_D * 512; idx += 256) {
        int d = idx / 512, c4 = idx % 512;
        const float4 v = ((const float4*)(gate_w + (size_t)d * GW_STRIDE))[c4];
        ((float4*)(sW + d * 2048))[c4] = v;
    }
    // ---- load A tables ----
    for (int idx = tid; idx < 4096; idx += 256) sA[idx] = d_A[idx];
    // ---- init h: blade 0 = 1 ----
    for (int idx = tid; idx < DD * HPAD; idx += 256) sH0[idx] = 0.f;
    __syncthreads();
    for (int idx = tid; idx < DD; idx += 256) sH0[idx * HPAD] = 1.f;
    __syncthreads();

    const int dB = tid >> 2;            // phase-B versor
    const int k0 = (tid & 3) * 8;       // phase-B blade octet

    #pragma unroll 1
    for (int t = 0; t < TT; t++) {
        float* sHc = (t & 1) ? sH1 : sH0;
        float* sHn = (t & 1) ? sH0 : sH1;
        const int c = __ldg(x + b * TT + t) & 3;

        // ================= Phase A: gate logits =================
        float acc[8];
        #pragma unroll
        for (int i = 0; i < 8; i++) acc[i] = 0.f;

        #pragma unroll 2
        for (int ch = 0; ch < 16; ch++) {
            const int j = ch * 128 + lane * 4;
            const float4 hv = *(const float4*)(sHc + (j >> 5) * HPAD + (j & 31));
            #pragma unroll
            for (int i = 0; i < 8; i++) {
                const int d = w + 8 * i;       // rows d<24 (i<3) cached in SMEM
                float4 wv;
                if (i < 3) wv = *(const float4*)(sW + d * 2048 + j);
                else       wv = *(const float4*)(gate_w + (size_t)d * GW_STRIDE + j);
                acc[i] = fmaf(wv.x, hv.x, fmaf(wv.y, hv.y,
                         fmaf(wv.z, hv.z, fmaf(wv.w, hv.w, acc[i]))));
            }
        }
        #pragma unroll
        for (int off = 16; off; off >>= 1) {
            #pragma unroll
            for (int i = 0; i < 8; i++)
                acc[i] += __shfl_xor_sync(0xffffffffu, acc[i], off);
        }
        if (lane == 0) {
            #pragma unroll
            for (int i = 0; i < 8; i++) {
                const int d = w + 8 * i;
                const float l = acc[i] + d_gr[c * 64 + d];
                sG[d] = __fdividef(1.f, 1.f + __expf(-l));
            }
        }
        __syncthreads();

        // ========== Phase B: geometric product + blend + norm ==========
        {
            const float* hc = sHc + dB * HPAD;
            float hr[32];
            #pragma unroll
            for (int q = 0; q < 8; q++) {
                const float4 t4 = *(const float4*)(hc + q * 4);
                hr[q * 4 + 0] = t4.x; hr[q * 4 + 1] = t4.y;
                hr[q * 4 + 2] = t4.z; hr[q * 4 + 3] = t4.w;
            }
            float4 n0 = make_float4(0.f, 0.f, 0.f, 0.f);
            float4 n1 = make_float4(0.f, 0.f, 0.f, 0.f);
            const float* Ac = sA + c * 1024 + k0;
            #pragma unroll
            for (int j = 0; j < 32; j++) {
                const float hj = hr[j];
                const float4 a0 = *(const float4*)(Ac + j * 32);
                const float4 a1 = *(const float4*)(Ac + j * 32 + 4);
                n0.x = fmaf(a0.x, hj, n0.x); n0.y = fmaf(a0.y, hj, n0.y);
                n0.z = fmaf(a0.z, hj, n0.z); n0.w = fmaf(a0.w, hj, n0.w);
                n1.x = fmaf(a1.x, hj, n1.x); n1.y = fmaf(a1.y, hj, n1.y);
                n1.z = fmaf(a1.z, hj, n1.z); n1.w = fmaf(a1.w, hj, n1.w);
            }
            const float g  = sG[dB];
            const float om = 1.f - g;
            const float4 hb0 = *(const float4*)(hc + k0);
            const float4 hb1 = *(const float4*)(hc + k0 + 4);
            float4 v0, v1;
            v0.x = om * hb0.x + g * n0.x; v0.y = om * hb0.y + g * n0.y;
            v0.z = om * hb0.z + g * n0.z; v0.w = om * hb0.w + g * n0.w;
            v1.x = om * hb1.x + g * n1.x; v1.y = om * hb1.y + g * n1.y;
            v1.z = om * hb1.z + g * n1.z; v1.w = om * hb1.w + g * n1.w;
            float ss = v0.x * v0.x + v0.y * v0.y + v0.z * v0.z + v0.w * v0.w
                     + v1.x * v1.x + v1.y * v1.y + v1.z * v1.z + v1.w * v1.w;
            ss += __shfl_xor_sync(0xffffffffu, ss, 1);
            ss += __shfl_xor_sync(0xffffffffu, ss, 2);
            const float sc = __fdividef(1.f, sqrtf(ss) + 1e-8f);
            v0.x *= sc; v0.y *= sc; v0.z *= sc; v0.w *= sc;
            v1.x *= sc; v1.y *= sc; v1.z *= sc; v1.w *= sc;
            *(float4*)(sHn + dB * HPAD + k0)     = v0;
            *(float4*)(sHn + dB * HPAD + k0 + 4) = v1;
        }
        __syncthreads();
    }

    // ================= Head: z = h@w1.T + b1, LN, relu, @w2.T + b2 ===========
    const float* hF = sH0;   // TT even -> final state in sH0
    #pragma unroll 1
    for (int rr = 0; rr < 16; rr++) {
        const int r = w * 16 + rr;
        float a = 0.f;
        #pragma unroll 4
        for (int ch = 0; ch < 16; ch++) {
            const int j = ch * 128 + lane * 4;
            const float4 hv = *(const float4*)(hF + (j >> 5) * HPAD + (j & 31));
            const float4 wv = *(const float4*)(w1 + (size_t)r * 2048 + j);
            a = fmaf(wv.x, hv.x, fmaf(wv.y, hv.y,
                fmaf(wv.z, hv.z, fmaf(wv.w, hv.w, a))));
        }
        #pragma unroll
        for (int off = 16; off; off >>= 1) a += __shfl_xor_sync(0xffffffffu, a, off);
        if (lane == 0) sZ[r] = a + __ldg(b1 + r);
    }
    __syncthreads();

    if (w == 0) {
        float zv[4];
        #pragma unroll
        for (int q = 0; q < 4; q++) zv[q] = sZ[lane + 32 * q];
        float s1 = zv[0] + zv[1] + zv[2] + zv[3];
        float s2 = zv[0] * zv[0] + zv[1] * zv[1] + zv[2] * zv[2] + zv[3] * zv[3];
        #pragma unroll
        for (int off = 16; off; off >>= 1) {
            s1 += __shfl_xor_sync(0xffffffffu, s1, off);
            s2 += __shfl_xor_sync(0xffffffffu, s2, off);
        }
        const float mu  = s1 * (1.f / 128.f);
        const float var = s2 * (1.f / 128.f) - mu * mu;
        const float rs  = __fdividef(1.f, sqrtf(var + 1e-5f));
        float o0 = 0.f, o1 = 0.f;
        #pragma unroll
        for (int q = 0; q < 4; q++) {
            const int r = lane + 32 * q;
            float zn = (zv[q] - mu) * rs * __ldg(ln_g + r) + __ldg(ln_b + r);
            zn = fmaxf(zn, 0.f);
            o0 = fmaf(zn, __ldg(w2 + r), o0);
            o1 = fmaf(zn, __ldg(w2 + 128 + r), o1);
        }
        #pragma unroll
        for (int off = 16; off; off >>= 1) {
            o0 += __shfl_xor_sync(0xffffffffu, o0, off);
            o1 += __shfl_xor_sync(0xffffffffu, o1, off);
        }
        if (lane == 0) {
            out[b * 2 + 0] = o0 + __ldg(b2 + 0);
            out[b * 2 + 1] = o1 + __ldg(b2 + 1);
        }
    }
}

extern "C" void kernel_launch(void* const* d_in, const int* in_sizes, int n_in,
                              void* d_out, int out_size) {
    const int*   x      = (const int*)  d_in[0];
    const float* emb    = (const float*)d_in[1];
    const float* gate_w = (const float*)d_in[2];
    const float* gate_b = (const float*)d_in[3];
    const float* w1     = (const float*)d_in[4];
    const float* b1     = (const float*)d_in[5];
    const float* ln_g   = (const float*)d_in[6];
    const float* ln_b   = (const float*)d_in[7];
    const float* w2     = (const float*)d_in[8];
    const float* b2     = (const float*)d_in[9];
    const float* gp     = (const float*)d_in[10];
    float* out = (float*)d_out;

    setup_kernel<<<1, 128>>>(emb, gate_w, gate_b, gp);

    const int smem_bytes = (CACHE_D * 2048 + 2 * DD * HPAD + 4096 + 64 + 128) * 4;
    cudaFuncSetAttribute(versor_main_kernel,
                         cudaFuncAttributeMaxDynamicSharedMemorySize, smem_bytes);
    versor_main_kernel<<<BB, 256, smem_bytes>>>(x, gate_w, w1, b1, ln_g, ln_b,
                                                w2, b2, out);
}

// round 2
// speedup vs baseline: 1.0165x; 1.0165x over previous
#include <cuda_runtime.h>
#include <cuda_fp16.h>
#include <math.h>

#define BB 128
#define TT 512
#define DD 64
#define GW_STRIDE 2080
#define NT 512

// Precomputed tables (setup kernel -> main kernel)
__device__ float  d_A[4 * 32 * 32];    // A[c][j][k] = sum_i rnorm[c][i] * T[i][j][k]
__device__ float  d_gr[4 * 64];        // gate_b[d] + sum_i gate_w[d][2048+i] * rnorm[c][i]
__device__ __half d_gwt[2048 * 64];    // transposed fp16 gate weights: [j][d]

__global__ void setup_kernel(const float* __restrict__ emb,
                             const float* __restrict__ gate_w,
                             const float* __restrict__ gate_b,
                             const float* __restrict__ gp) {
    __shared__ float r[4][32];
    int t = threadIdx.x;           // 256 threads
    if (t < 128) {
        int c = t >> 5, i = t & 31;
        float v = emb[c * 32 + i];
        float s = v * v;
        #pragma unroll
        for (int off = 16; off; off >>= 1) s += __shfl_xor_sync(0xffffffffu, s, off);
        r[c][i] = v / (sqrtf(s) + 1e-8f);
    }
    __syncthreads();

    // A table: 4096 entries
    for (int idx = t; idx < 4096; idx += 256) {
        int cc = idx >> 10, jk = idx & 1023;
        float acc = 0.f;
        #pragma unroll
        for (int ii = 0; ii < 32; ii++) acc += r[cc][ii] * gp[ii * 1024 + jk];
        d_A[idx] = acc;
    }
    // gate r-term table (+ bias folded)
    for (int idx = t; idx < 256; idx += 256) {
        int cc = idx >> 6, d = idx & 63;
        float acc = gate_b[d];
        #pragma unroll
        for (int ii = 0; ii < 32; ii++)
            acc += gate_w[d * GW_STRIDE + 2048 + ii] * r[cc][ii];
        d_gr[idx] = acc;
    }
    // transposed fp16 weights
    for (int idx = t; idx < 2048 * 64; idx += 256) {
        int j = idx >> 6, d = idx & 63;
        d_gwt[idx] = __float2half_rn(gate_w[(size_t)d * GW_STRIDE + j]);
    }
}

// SMEM float offsets
#define OFF_H   49152          // sWt = 1536*64 halves = 49152 floats
#define OFF_A   (OFF_H + 2048)
#define OFF_P   (OFF_A + 4096)
#define OFF_G   (OFF_P + 1024)
#define OFF_GR  (OFF_G + 64)
#define SMEM_FLOATS (OFF_GR + 256)   // 56640 floats = 226560 B

__global__ void __launch_bounds__(NT, 1)
versor_main_kernel(const int* __restrict__ x,
                   const float* __restrict__ w1,
                   const float* __restrict__ b1,
                   const float* __restrict__ ln_g,
                   const float* __restrict__ ln_b,
                   const float* __restrict__ w2,
                   const float* __restrict__ b2,
                   float* __restrict__ out) {
    extern __shared__ float sm[];
    __half* sWt = (__half*)sm;            // [j<1536][64] fp16
    float* sH  = sm + OFF_H;              // h state [64][32] flat
    float* sA  = sm + OFF_A;              // 4x32x32
    float* sP  = sm + OFF_P;              // partials [16][64]
    float* sG  = sm + OFF_G;              // gates [64]
    float* sGr = sm + OFF_GR;             // 4x64
    float* sZ  = sP;                      // alias (head only)

    const int tid  = threadIdx.x;
    const int lane = tid & 31;
    const int w    = tid >> 5;            // warp 0..15
    const int q    = lane >> 3;           // quarter-warp 0..3
    const int r8   = lane & 7;            // covers rows r8*8 .. r8*8+7
    const int b    = blockIdx.x;

    // ---- init SMEM ----
    for (int idx = tid; idx < 12288; idx += NT)           // 1536*64 halves as uint4
        ((uint4*)sWt)[idx] = ((const uint4*)d_gwt)[idx];
    for (int idx = tid; idx < 4096; idx += NT) sA[idx] = d_A[idx];
    for (int idx = tid; idx < 256;  idx += NT) sGr[idx] = d_gr[idx];
    for (int idx = tid; idx < 2048; idx += NT) sH[idx] = ((idx & 31) == 0) ? 1.f : 0.f;
    __syncthreads();

    const int dB = tid >> 3;              // phase-B versor 0..63
    const int k0 = (tid & 7) * 4;         // phase-B blade quad
    const int jc_base = w * 96 + q;       // cached j slice  [w*96, w*96+96)
    const int js_base = 1536 + w * 32 + q;// streamed j slice

    #pragma unroll 1
    for (int t = 0; t < TT; t++) {
        const int c = __ldg(x + b * TT + t) & 3;

        // ================= Phase A: gate partial dots =================
        float acc[8];
        #pragma unroll
        for (int i = 0; i < 8; i++) acc[i] = 0.f;

        // cached columns (SMEM fp16)
        #pragma unroll 8
        for (int tt = 0; tt < 24; tt++) {
            const int j = jc_base + 4 * tt;
            const float hj = sH[j];
            const uint4 wv = ((const uint4*)sWt)[j * 8 + r8];
            const half2* hw = (const half2*)&wv;
            const float2 f0 = __half22float2(hw[0]);
            const float2 f1 = __half22float2(hw[1]);
            const float2 f2 = __half22float2(hw[2]);
            const float2 f3 = __half22float2(hw[3]);
            acc[0] = fmaf(f0.x, hj, acc[0]); acc[1] = fmaf(f0.y, hj, acc[1]);
            acc[2] = fmaf(f1.x, hj, acc[2]); acc[3] = fmaf(f1.y, hj, acc[3]);
            acc[4] = fmaf(f2.x, hj, acc[4]); acc[5] = fmaf(f2.y, hj, acc[5]);
            acc[6] = fmaf(f3.x, hj, acc[6]); acc[7] = fmaf(f3.y, hj, acc[7]);
        }
        // streamed columns (global fp16, served from L2)
        #pragma unroll 8
        for (int tt = 0; tt < 8; tt++) {
            const int j = js_base + 4 * tt;
            const float hj = sH[j];
            const uint4 wv = __ldg((const uint4*)d_gwt + j * 8 + r8);
            const half2* hw = (const half2*)&wv;
            const float2 f0 = __half22float2(hw[0]);
            const float2 f1 = __half22float2(hw[1]);
            const float2 f2 = __half22float2(hw[2]);
            const float2 f3 = __half22float2(hw[3]);
            acc[0] = fmaf(f0.x, hj, acc[0]); acc[1] = fmaf(f0.y, hj, acc[1]);
            acc[2] = fmaf(f1.x, hj, acc[2]); acc[3] = fmaf(f1.y, hj, acc[3]);
            acc[4] = fmaf(f2.x, hj, acc[4]); acc[5] = fmaf(f2.y, hj, acc[5]);
            acc[6] = fmaf(f3.x, hj, acc[6]); acc[7] = fmaf(f3.y, hj, acc[7]);
        }
        // reduce over the 4 quarter-warps (same r8, different q)
        #pragma unroll
        for (int i = 0; i < 8; i++) {
            acc[i] += __shfl_xor_sync(0xffffffffu, acc[i], 8);
            acc[i] += __shfl_xor_sync(0xffffffffu, acc[i], 16);
        }
        if (q == 0) {
            #pragma unroll
            for (int i = 0; i < 8; i++) sP[w * 64 + r8 * 8 + i] = acc[i];
        }
        __syncthreads();

        // ---- load this thread's versor into registers (pre-write snapshot) ----
        float hr[32];
        {
            const float* hrow = sH + dB * 32;
            #pragma unroll
            for (int qq = 0; qq < 8; qq++) {
                const float4 v = *(const float4*)(hrow + qq * 4);
                hr[qq * 4 + 0] = v.x; hr[qq * 4 + 1] = v.y;
                hr[qq * 4 + 2] = v.z; hr[qq * 4 + 3] = v.w;
            }
        }
        // ---- stage 2: reduce partials -> sigmoid gate ----
        if (tid < 64) {
            float s = sGr[c * 64 + tid];
            #pragma unroll
            for (int ww = 0; ww < 16; ww++) s += sP[ww * 64 + tid];
            sG[tid] = __fdividef(1.f, 1.f + __expf(-s));
        }
        __syncthreads();

        // ========== Phase B: geometric product + blend + norm ==========
        {
            const float* Ac = sA + c * 1024 + k0;
            float4 n = make_float4(0.f, 0.f, 0.f, 0.f);
            #pragma unroll
            for (int j = 0; j < 32; j++) {
                const float hj = hr[j];
                const float4 a = *(const float4*)(Ac + j * 32);
                n.x = fmaf(a.x, hj, n.x); n.y = fmaf(a.y, hj, n.y);
                n.z = fmaf(a.z, hj, n.z); n.w = fmaf(a.w, hj, n.w);
            }
            const float g  = sG[dB];
            const float om = 1.f - g;
            float4 v;
            v.x = om * hr[k0 + 0] + g * n.x;
            v.y = om * hr[k0 + 1] + g * n.y;
            v.z = om * hr[k0 + 2] + g * n.z;
            v.w = om * hr[k0 + 3] + g * n.w;
            float ss = v.x * v.x + v.y * v.y + v.z * v.z + v.w * v.w;
            ss += __shfl_xor_sync(0xffffffffu, ss, 1);
            ss += __shfl_xor_sync(0xffffffffu, ss, 2);
            ss += __shfl_xor_sync(0xffffffffu, ss, 4);
            const float sc = __fdividef(1.f, sqrtf(ss) + 1e-8f);
            v.x *= sc; v.y *= sc; v.z *= sc; v.w *= sc;
            *(float4*)(sH + dB * 32 + k0) = v;
        }
        __syncthreads();
    }

    // ================= Head: z = h@w1.T + b1, LN, relu, @w2.T + b2 ===========
    #pragma unroll 1
    for (int rr = 0; rr < 8; rr++) {
        const int r = w * 8 + rr;
        float a = 0.f;
        #pragma unroll 4
        for (int ch = 0; ch < 16; ch++) {
            const int j = ch * 128 + lane * 4;
            const float4 hv = *(const float4*)(sH + j);
            const float4 wv = *(const float4*)(w1 + (size_t)r * 2048 + j);
            a = fmaf(wv.x, hv.x, fmaf(wv.y, hv.y,
                fmaf(wv.z, hv.z, fmaf(wv.w, hv.w, a))));
        }
        #pragma unroll
        for (int off = 16; off; off >>= 1) a += __shfl_xor_sync(0xffffffffu, a, off);
        if (lane == 0) sZ[r] = a + __ldg(b1 + r);
    }
    __syncthreads();

    if (w == 0) {
        float zv[4];
        #pragma unroll
        for (int qq = 0; qq < 4; qq++) zv[qq] = sZ[lane + 32 * qq];
        float s1 = zv[0] + zv[1] + zv[2] + zv[3];
        float s2 = zv[0] * zv[0] + zv[1] * zv[1] + zv[2] * zv[2] + zv[3] * zv[3];
        #pragma unroll
        for (int off = 16; off; off >>= 1) {
            s1 += __shfl_xor_sync(0xffffffffu, s1, off);
            s2 += __shfl_xor_sync(0xffffffffu, s2, off);
        }
        const float mu  = s1 * (1.f / 128.f);
        const float var = s2 * (1.f / 128.f) - mu * mu;
        const float rs  = __fdividef(1.f, sqrtf(var + 1e-5f));
        float o0 = 0.f, o1 = 0.f;
        #pragma unroll
        for (int qq = 0; qq < 4; qq++) {
            const int r = lane + 32 * qq;
            float zn = (zv[qq] - mu) * rs * __ldg(ln_g + r) + __ldg(ln_b + r);
            zn = fmaxf(zn, 0.f);
            o0 = fmaf(zn, __ldg(w2 + r), o0);
            o1 = fmaf(zn, __ldg(w2 + 128 + r), o1);
        }
        #pragma unroll
        for (int off = 16; off; off >>= 1) {
            o0 += __shfl_xor_sync(0xffffffffu, o0, off);
            o1 += __shfl_xor_sync(0xffffffffu, o1, off);
        }
        if (lane == 0) {
            out[b * 2 + 0] = o0 + __ldg(b2 + 0);
            out[b * 2 + 1] = o1 + __ldg(b2 + 1);
        }
    }
}

extern "C" void kernel_launch(void* const* d_in, const int* in_sizes, int n_in,
                              void* d_out, int out_size) {
    const int*   x      = (const int*)  d_in[0];
    const float* emb    = (const float*)d_in[1];
    const float* gate_w = (const float*)d_in[2];
    const float* gate_b = (const float*)d_in[3];
    const float* w1     = (const float*)d_in[4];
    const float* b1     = (const float*)d_in[5];
    const float* ln_g   = (const float*)d_in[6];
    const float* ln_b   = (const float*)d_in[7];
    const float* w2     = (const float*)d_in[8];
    const float* b2     = (const float*)d_in[9];
    const float* gp     = (const float*)d_in[10];
    float* out = (float*)d_out;

    setup_kernel<<<1, 256>>>(emb, gate_w, gate_b, gp);

    const int smem_bytes = SMEM_FLOATS * 4;
    cudaFuncSetAttribute(versor_main_kernel,
                         cudaFuncAttributeMaxDynamicSharedMemorySize, smem_bytes);
    versor_main_kernel<<<BB, NT, smem_bytes>>>(x, w1, b1, ln_g, ln_b,
                                               w2, b2, out);
}

// round 3
// speedup vs baseline: 1.2244x; 1.2045x over previous
#include <cuda_runtime.h>
#include <cuda_fp16.h>
#include <math.h>

#define BB 128
#define TT 512
#define GW_STRIDE 2080
#define NT 512

#define SROWS 704                 // fp32 rows cached in SMEM   [0,704)
#define RROWS 320                 // fp32 rows in registers     [704,1024)
#define XBASE 1024                // fp16 rows streamed from L2 [1024,2048)

// SMEM float offsets
#define OFF_H0 45056              // SROWS*64
#define OFF_H1 47104
#define OFF_A  49152
#define OFF_P1 53248
#define OFF_P2 54272
#define OFF_G  55296
#define OFF_GR 55360
#define OFF_X  55616
#define SMEM_FLOATS 56128         // 224512 bytes

__device__ float  d_A[4096];          // A[c][j][k]
__device__ float  d_gr[256];          // gate_b + r-term, [c][d]
__device__ float  d_gw32[2048 * 64];  // transposed fp32 weights [j][d]
__device__ __half d_gw16[2048 * 64];  // transposed fp16 weights [j][d]

static __device__ __forceinline__ unsigned long long pk2(float a, float b) {
    unsigned long long r;
    asm("mov.b64 %0, {%1,%2};" : "=l"(r) : "f"(a), "f"(b));
    return r;
}
static __device__ __forceinline__ void ffma2(unsigned long long& d,
                                             unsigned long long a,
                                             unsigned long long b) {
    asm("fma.rn.f32x2 %0, %1, %2, %0;" : "+l"(d) : "l"(a), "l"(b));
}
static __device__ __forceinline__ float2 upk2(unsigned long long v) {
    float lo, hi;
    asm("mov.b64 {%0,%1}, %2;" : "=f"(lo), "=f"(hi) : "l"(v));
    return make_float2(lo, hi);
}

__global__ void setup_kernel(const float* __restrict__ emb,
                             const float* __restrict__ gate_w,
                             const float* __restrict__ gate_b,
                             const float* __restrict__ gp) {
    __shared__ float r[4][32];
    int t = threadIdx.x;           // 256 threads
    if (t < 128) {
        int c = t >> 5, i = t & 31;
        float v = emb[c * 32 + i];
        float s = v * v;
        #pragma unroll
        for (int off = 16; off; off >>= 1) s += __shfl_xor_sync(0xffffffffu, s, off);
        r[c][i] = v / (sqrtf(s) + 1e-8f);
    }
    __syncthreads();

    for (int idx = t; idx < 4096; idx += 256) {
        int cc = idx >> 10, jk = idx & 1023;
        float acc = 0.f;
        #pragma unroll
        for (int ii = 0; ii < 32; ii++) acc += r[cc][ii] * gp[ii * 1024 + jk];
        d_A[idx] = acc;
    }
    for (int idx = t; idx < 256; idx += 256) {
        int cc = idx >> 6, d = idx & 63;
        float acc = gate_b[d];
        #pragma unroll
        for (int ii = 0; ii < 32; ii++)
            acc += gate_w[d * GW_STRIDE + 2048 + ii] * r[cc][ii];
        d_gr[idx] = acc;
    }
    for (int idx = t; idx < 2048 * 64; idx += 256) {
        int j = idx >> 6, d = idx & 63;
        float v = gate_w[(size_t)d * GW_STRIDE + j];
        d_gw32[idx] = v;
        d_gw16[idx] = __float2half_rn(v);
    }
}

__global__ void __launch_bounds__(NT, 1)
versor_main_kernel(const int* __restrict__ x,
                   const float* __restrict__ w1,
                   const float* __restrict__ b1,
                   const float* __restrict__ ln_g,
                   const float* __restrict__ ln_b,
                   const float* __restrict__ w2,
                   const float* __restrict__ b2,
                   float* __restrict__ out) {
    extern __shared__ float sm[];
    float* sW  = sm;                  // [704][64] fp32
    float* sH0 = sm + OFF_H0;
    float* sH1 = sm + OFF_H1;
    float* sA  = sm + OFF_A;
    float* sP1 = sm + OFF_P1;         // quad-layout partials [16][64]
    float* sP2 = sm + OFF_P2;         // octet-layout partials [16][64]
    float* sG  = sm + OFF_G;
    float* sGr = sm + OFF_GR;
    int*   sX  = (int*)(sm + OFF_X);
    float* sZ  = sP1;                 // head alias

    const int tid  = threadIdx.x;
    const int lane = tid & 31;
    const int w    = tid >> 5;        // warp 0..15
    const int h16  = lane >> 4;       // half-warp
    const int q15  = lane & 15;
    const int q    = lane >> 3;       // quarter-warp
    const int r8   = lane & 7;
    const int b    = blockIdx.x;

    // ---- init SMEM ----
    for (int idx = tid; idx < SROWS * 16; idx += NT)
        ((float4*)sW)[idx] = ((const float4*)d_gw32)[idx];
    for (int idx = tid; idx < 4096; idx += NT) sA[idx] = d_A[idx];
    for (int idx = tid; idx < 256;  idx += NT) sGr[idx] = d_gr[idx];
    for (int idx = tid; idx < 2048; idx += NT) sH0[idx] = ((idx & 31) == 0) ? 1.f : 0.f;
    for (int idx = tid; idx < TT;   idx += NT) sX[idx] = x[b * TT + idx];

    // ---- register-resident fp32 weights: 10 j x 4 d per thread, pre-packed ----
    unsigned long long wpk[20];
    {
        const int jb = SROWS + w * 20 + h16 * 10;
        #pragma unroll
        for (int jj = 0; jj < 10; jj++) {
            const float4 v = *(const float4*)(d_gw32 + (size_t)(jb + jj) * 64 + q15 * 4);
            wpk[2 * jj]     = pk2(v.x, v.y);
            wpk[2 * jj + 1] = pk2(v.z, v.w);
        }
    }
    __syncthreads();

    const int dB = tid >> 3;          // phase-B versor
    const int k0 = (tid & 7) * 4;     // phase-B blade quad

    #pragma unroll 1
    for (int t = 0; t < TT; t++) {
        float* hc = (t & 1) ? sH1 : sH0;
        float* hn = (t & 1) ? sH0 : sH1;
        const int c = sX[t];

        // ============ Phase A: gate partial dots ============
        // streamed fp16 rows (octet-d layout, scalar FFMA after cvt)
        float a8[8];
        #pragma unroll
        for (int i = 0; i < 8; i++) a8[i] = 0.f;
        {
            const int jb = XBASE + w * 64 + q;
            #pragma unroll 4
            for (int it = 0; it < 16; it++) {
                const int j = jb + 4 * it;
                const float hj = hc[j];
                const uint4 wv = __ldg((const uint4*)d_gw16 + j * 8 + r8);
                const half2* hw = (const half2*)&wv;
                const float2 f0 = __half22float2(hw[0]);
                const float2 f1 = __half22float2(hw[1]);
                const float2 f2 = __half22float2(hw[2]);
                const float2 f3 = __half22float2(hw[3]);
                a8[0] = fmaf(f0.x, hj, a8[0]); a8[1] = fmaf(f0.y, hj, a8[1]);
                a8[2] = fmaf(f1.x, hj, a8[2]); a8[3] = fmaf(f1.y, hj, a8[3]);
                a8[4] = fmaf(f2.x, hj, a8[4]); a8[5] = fmaf(f2.y, hj, a8[5]);
                a8[6] = fmaf(f3.x, hj, a8[6]); a8[7] = fmaf(f3.y, hj, a8[7]);
            }
        }
        // register fp32 rows (quad-d layout, f32x2)
        unsigned long long qa0 = 0ull, qa1 = 0ull, qa2 = 0ull, qa3 = 0ull;
        {
            const int jb = SROWS + w * 20 + h16 * 10;
            #pragma unroll
            for (int jj = 0; jj < 10; jj += 2) {
                const float hj0 = hc[jb + jj];
                const unsigned long long hp0 = pk2(hj0, hj0);
                ffma2(qa0, wpk[2 * jj],     hp0);
                ffma2(qa1, wpk[2 * jj + 1], hp0);
                const float hj1 = hc[jb + jj + 1];
                const unsigned long long hp1 = pk2(hj1, hj1);
                ffma2(qa2, wpk[2 * jj + 2], hp1);
                ffma2(qa3, wpk[2 * jj + 3], hp1);
            }
        }
        // SMEM fp32 rows (quad-d layout, f32x2), 2 j per warp-iter
        {
            const int jb = w * 44;
            #pragma unroll 11
            for (int it = 0; it < 22; it += 2) {
                {
                    const int j = jb + 2 * it + h16;
                    const float hj = hc[j];
                    const unsigned long long hp = pk2(hj, hj);
                    const ulonglong2 wv = *(const ulonglong2*)(sW + j * 64 + q15 * 4);
                    ffma2(qa0, wv.x, hp);
                    ffma2(qa1, wv.y, hp);
                }
                {
                    const int j = jb + 2 * (it + 1) + h16;
                    const float hj = hc[j];
                    const unsigned long long hp = pk2(hj, hj);
                    const ulonglong2 wv = *(const ulonglong2*)(sW + j * 64 + q15 * 4);
                    ffma2(qa2, wv.x, hp);
                    ffma2(qa3, wv.y, hp);
                }
            }
        }
        // reduce quad-layout partials: lanes h16=0/1 hold same d-quad
        {
            float2 f0 = upk2(qa0), f1 = upk2(qa1), f2 = upk2(qa2), f3 = upk2(qa3);
            float4 s4;
            s4.x = f0.x + f2.x; s4.y = f0.y + f2.y;
            s4.z = f1.x + f3.x; s4.w = f1.y + f3.y;
            s4.x += __shfl_xor_sync(0xffffffffu, s4.x, 16);
            s4.y += __shfl_xor_sync(0xffffffffu, s4.y, 16);
            s4.z += __shfl_xor_sync(0xffffffffu, s4.z, 16);
            s4.w += __shfl_xor_sync(0xffffffffu, s4.w, 16);
            if (h16 == 0) *(float4*)(sP1 + w * 64 + q15 * 4) = s4;
        }
        // reduce octet-layout partials: lanes with same r8 across q
        {
            #pragma unroll
            for (int i = 0; i < 8; i++) {
                a8[i] += __shfl_xor_sync(0xffffffffu, a8[i], 8);
                a8[i] += __shfl_xor_sync(0xffffffffu, a8[i], 16);
            }
            if (q == 0) {
                *(float4*)(sP2 + w * 64 + r8 * 8)     = make_float4(a8[0], a8[1], a8[2], a8[3]);
                *(float4*)(sP2 + w * 64 + r8 * 8 + 4) = make_float4(a8[4], a8[5], a8[6], a8[7]);
            }
        }
        __syncthreads();

        // ---- stage 2 (warps 0,1): reduce partials -> sigmoid gate ----
        if (tid < 64) {
            float s = sGr[c * 64 + tid];
            #pragma unroll
            for (int ww = 0; ww < 16; ww++)
                s += sP1[ww * 64 + tid] + sP2[ww * 64 + tid];
            sG[tid] = __fdividef(1.f, 1.f + __expf(-s));
        }

        // ---- geometric product (g-independent): n = A_c @ h[dB] ----
        unsigned long long n0 = 0ull, n1 = 0ull;
        {
            const float* hrow = hc + dB * 32;
            const ulonglong2* Ap = (const ulonglong2*)(sA + c * 1024) + (tid & 7);
            #pragma unroll
            for (int j = 0; j < 32; j++) {
                const float hj = hrow[j];
                const unsigned long long hp = pk2(hj, hj);
                const ulonglong2 av = Ap[j * 8];
                ffma2(n0, av.x, hp);
                ffma2(n1, av.y, hp);
            }
        }
        __syncthreads();

        // ---- blend + normalize + store ----
        {
            const float g  = sG[dB];
            const float om = 1.f - g;
            const float4 hq = *(const float4*)(hc + dB * 32 + k0);
            const float2 na = upk2(n0);
            const float2 nb = upk2(n1);
            float4 v;
            v.x = om * hq.x + g * na.x;
            v.y = om * hq.y + g * na.y;
            v.z = om * hq.z + g * nb.x;
            v.w = om * hq.w + g * nb.y;
            float ss = v.x * v.x + v.y * v.y + v.z * v.z + v.w * v.w;
            ss += __shfl_xor_sync(0xffffffffu, ss, 1);
            ss += __shfl_xor_sync(0xffffffffu, ss, 2);
            ss += __shfl_xor_sync(0xffffffffu, ss, 4);
            const float sc = __fdividef(1.f, sqrtf(ss) + 1e-8f);
            v.x *= sc; v.y *= sc; v.z *= sc; v.w *= sc;
            *(float4*)(hn + dB * 32 + k0) = v;
        }
        __syncthreads();
    }

    // ============ Head: z = h@w1.T + b1, LN, relu, @w2.T + b2 ============
    const float* hF = sH0;   // TT even -> final state in sH0
    #pragma unroll 1
    for (int rr = 0; rr < 8; rr++) {
        const int r = w * 8 + rr;
        float a = 0.f;
        #pragma unroll 4
        for (int ch = 0; ch < 16; ch++) {
            const int j = ch * 128 + lane * 4;
            const float4 hv = *(const float4*)(hF + j);
            const float4 wv = *(const float4*)(w1 + (size_t)r * 2048 + j);
            a = fmaf(wv.x, hv.x, fmaf(wv.y, hv.y,
                fmaf(wv.z, hv.z, fmaf(wv.w, hv.w, a))));
        }
        #pragma unroll
        for (int off = 16; off; off >>= 1) a += __shfl_xor_sync(0xffffffffu, a, off);
        if (lane == 0) sZ[r] = a + __ldg(b1 + r);
    }
    __syncthreads();

    if (w == 0) {
        float zv[4];
        #pragma unroll
        for (int qq = 0; qq < 4; qq++) zv[qq] = sZ[lane + 32 * qq];
        float s1 = zv[0] + zv[1] + zv[2] + zv[3];
        float s2 = zv[0] * zv[0] + zv[1] * zv[1] + zv[2] * zv[2] + zv[3] * zv[3];
        #pragma unroll
        for (int off = 16; off; off >>= 1) {
            s1 += __shfl_xor_sync(0xffffffffu, s1, off);
            s2 += __shfl_xor_sync(0xffffffffu, s2, off);
        }
        const float mu  = s1 * (1.f / 128.f);
        const float var = s2 * (1.f / 128.f) - mu * mu;
        const float rs  = __fdividef(1.f, sqrtf(var + 1e-5f));
        float o0 = 0.f, o1 = 0.f;
        #pragma unroll
        for (int qq = 0; qq < 4; qq++) {
            const int r = lane + 32 * qq;
            float zn = (zv[qq] - mu) * rs * __ldg(ln_g + r) + __ldg(ln_b + r);
            zn = fmaxf(zn, 0.f);
            o0 = fmaf(zn, __ldg(w2 + r), o0);
            o1 = fmaf(zn, __ldg(w2 + 128 + r), o1);
        }
        #pragma unroll
        for (int off = 16; off; off >>= 1) {
            o0 += __shfl_xor_sync(0xffffffffu, o0, off);
            o1 += __shfl_xor_sync(0xffffffffu, o1, off);
        }
        if (lane == 0) {
            out[b * 2 + 0] = o0 + __ldg(b2 + 0);
            out[b * 2 + 1] = o1 + __ldg(b2 + 1);
        }
    }
}

extern "C" void kernel_launch(void* const* d_in, const int* in_sizes, int n_in,
                              void* d_out, int out_size) {
    const int*   x      = (const int*)  d_in[0];
    const float* emb    = (const float*)d_in[1];
    const float* gate_w = (const float*)d_in[2];
    const float* gate_b = (const float*)d_in[3];
    const float* w1     = (const float*)d_in[4];
    const float* b1     = (const float*)d_in[5];
    const float* ln_g   = (const float*)d_in[6];
    const float* ln_b   = (const float*)d_in[7];
    const float* w2     = (const float*)d_in[8];
    const float* b2     = (const float*)d_in[9];
    const float* gp     = (const float*)d_in[10];
    float* out = (float*)d_out;

    setup_kernel<<<1, 256>>>(emb, gate_w, gate_b, gp);

    const int smem_bytes = SMEM_FLOATS * 4;
    cudaFuncSetAttribute(versor_main_kernel,
                         cudaFuncAttributeMaxDynamicSharedMemorySize, smem_bytes);
    versor_main_kernel<<<BB, NT, smem_bytes>>>(x, w1, b1, ln_g, ln_b,
                                               w2, b2, out);
}

// round 4
// speedup vs baseline: 1.5239x; 1.2447x over previous
#include <cuda_runtime.h>
#include <cuda_fp16.h>
#include <math.h>

#define BB 128
#define TT 512
#define GW_STRIDE 2080
#define NT 512

#define RROWS 320                 // fp32 rows in registers       [0,320)
#define CBASE 320                 // fp16 rows cached in SMEM     [320,1664)
#define CROWS 1344
#define XBASE 1664                // fp16 rows streamed from L2   [1664,2048)

// SMEM float offsets
#define OFF_H0 43008              // sW16 = 1344*64 halfs = 43008 floats
#define OFF_H1 45056
#define OFF_HD 47104              // duplicated half2 h (2048 half2)
#define OFF_A  49152
#define OFF_P1 53248
#define OFF_P2 54272
#define OFF_G  55296
#define OFF_GR 55360
#define OFF_X  55616
#define SMEM_FLOATS 56128         // 224512 bytes

__device__ float  d_A[4096];          // A[c][j][k]
__device__ float  d_gr[256];          // gate_b + r-term, [c][d]
__device__ float  d_gw32[2048 * 64];  // transposed fp32 weights [j][d]
__device__ __half d_gw16[2048 * 64];  // transposed fp16 weights [j][d]

static __device__ __forceinline__ unsigned long long pk2(float a, float b) {
    unsigned long long r;
    asm("mov.b64 %0, {%1,%2};" : "=l"(r) : "f"(a), "f"(b));
    return r;
}
static __device__ __forceinline__ void ffma2(unsigned long long& d,
                                             unsigned long long a,
                                             unsigned long long b) {
    asm("fma.rn.f32x2 %0, %1, %2, %0;" : "+l"(d) : "l"(a), "l"(b));
}
static __device__ __forceinline__ float2 upk2(unsigned long long v) {
    float lo, hi;
    asm("mov.b64 {%0,%1}, %2;" : "=f"(lo), "=f"(hi) : "l"(v));
    return make_float2(lo, hi);
}
static __device__ __forceinline__ unsigned h2u(__half2 h) {
    return *(unsigned*)&h;
}
static __device__ __forceinline__ __half2 u2h(unsigned u) {
    return *(__half2*)&u;
}

__global__ void setup_kernel(const float* __restrict__ emb,
                             const float* __restrict__ gate_w,
                             const float* __restrict__ gate_b,
                             const float* __restrict__ gp) {
    __shared__ float r[4][32];
    int t = threadIdx.x;           // 256 threads
    if (t < 128) {
        int c = t >> 5, i = t & 31;
        float v = emb[c * 32 + i];
        float s = v * v;
        #pragma unroll
        for (int off = 16; off; off >>= 1) s += __shfl_xor_sync(0xffffffffu, s, off);
        r[c][i] = v / (sqrtf(s) + 1e-8f);
    }
    __syncthreads();

    for (int idx = t; idx < 4096; idx += 256) {
        int cc = idx >> 10, jk = idx & 1023;
        float acc = 0.f;
        #pragma unroll
        for (int ii = 0; ii < 32; ii++) acc += r[cc][ii] * gp[ii * 1024 + jk];
        d_A[idx] = acc;
    }
    for (int idx = t; idx < 256; idx += 256) {
        int cc = idx >> 6, d = idx & 63;
        float acc = gate_b[d];
        #pragma unroll
        for (int ii = 0; ii < 32; ii++)
            acc += gate_w[d * GW_STRIDE + 2048 + ii] * r[cc][ii];
        d_gr[idx] = acc;
    }
    for (int idx = t; idx < 2048 * 64; idx += 256) {
        int j = idx >> 6, d = idx & 63;
        float v = gate_w[(size_t)d * GW_STRIDE + j];
        d_gw32[idx] = v;
        d_gw16[idx] = __float2half_rn(v);
    }
}

__global__ void __launch_bounds__(NT, 1)
versor_main_kernel(const int* __restrict__ x,
                   const float* __restrict__ w1,
                   const float* __restrict__ b1,
                   const float* __restrict__ ln_g,
                   const float* __restrict__ ln_b,
                   const float* __restrict__ w2,
                   const float* __restrict__ b2,
                   float* __restrict__ out) {
    extern __shared__ float sm[];
    __half*  sW16 = (__half*)sm;          // [1344][64] fp16 (local row idx)
    float*   sH0  = sm + OFF_H0;
    float*   sH1  = sm + OFF_H1;
    __half2* sHd  = (__half2*)(sm + OFF_HD);   // duplicated (h_j,h_j)
    float*   sA   = sm + OFF_A;
    float*   sP1  = sm + OFF_P1;          // quad-layout partials [16][64]
    float*   sP2  = sm + OFF_P2;          // octet-layout partials [16][64]
    float*   sG   = sm + OFF_G;
    float*   sGr  = sm + OFF_GR;
    int*     sX   = (int*)(sm + OFF_X);
    float*   sZ   = sP1;                  // head alias

    const int tid  = threadIdx.x;
    const int lane = tid & 31;
    const int w    = tid >> 5;            // warp 0..15
    const int h16  = lane >> 4;
    const int q15  = lane & 15;
    const int jway = lane >> 3;           // 0..3
    const int oct  = lane & 7;            // d-octet
    const int b    = blockIdx.x;

    // ---- init SMEM ----
    for (int idx = tid; idx < CROWS * 8; idx += NT)      // 1344*64 halfs as uint4
        ((uint4*)sW16)[idx] = ((const uint4*)(d_gw16 + CBASE * 64))[idx];
    for (int idx = tid; idx < 4096; idx += NT) sA[idx] = d_A[idx];
    for (int idx = tid; idx < 256;  idx += NT) sGr[idx] = d_gr[idx];
    for (int idx = tid; idx < 2048; idx += NT) {
        const float v = ((idx & 31) == 0) ? 1.f : 0.f;
        sH0[idx] = v;
        sHd[idx] = __floats2half2_rn(v, v);
    }
    for (int idx = tid; idx < TT; idx += NT) sX[idx] = x[b * TT + idx];

    // ---- register-resident fp32 weights: rows [0,320), 10 j x 4 d/thread ----
    unsigned long long wpk[20];
    {
        const int jb = w * 20 + h16 * 10;
        #pragma unroll
        for (int jj = 0; jj < 10; jj++) {
            const float4 v = *(const float4*)(d_gw32 + (size_t)(jb + jj) * 64 + q15 * 4);
            wpk[2 * jj]     = pk2(v.x, v.y);
            wpk[2 * jj + 1] = pk2(v.z, v.w);
        }
    }
    __syncthreads();

    const int dB = tid >> 3;              // phase-B versor
    const int k0 = (tid & 7) * 4;         // phase-B blade quad
    const __half2 hz = __float2half2_rn(0.f);

    #pragma unroll 1
    for (int t = 0; t < TT; t++) {
        float* hc = (t & 1) ? sH1 : sH0;
        float* hn = (t & 1) ? sH0 : sH1;
        const int c = sX[t];

        // ============ Phase A: gate partial dots ============
        // prefetch streamed fp16 rows (L2)
        uint4 xv[6];
        {
            const int rb = XBASE + w * 24 + jway;
            const uint4* g16 = (const uint4*)d_gw16;
            #pragma unroll
            for (int it = 0; it < 6; it++)
                xv[it] = __ldg(g16 + (rb + it * 4) * 8 + oct);
        }

        // register fp32 rows (quad-d layout, f32x2)
        unsigned long long qa0 = 0ull, qa1 = 0ull, qa2 = 0ull, qa3 = 0ull;
        {
            const int jb = w * 20 + h16 * 10;
            #pragma unroll
            for (int jj = 0; jj < 10; jj += 2) {
                const float hj0 = hc[jb + jj];
                const unsigned long long hp0 = pk2(hj0, hj0);
                ffma2(qa0, wpk[2 * jj],     hp0);
                ffma2(qa1, wpk[2 * jj + 1], hp0);
                const float hj1 = hc[jb + jj + 1];
                const unsigned long long hp1 = pk2(hj1, hj1);
                ffma2(qa2, wpk[2 * jj + 2], hp1);
                ffma2(qa3, wpk[2 * jj + 3], hp1);
            }
        }

        // SMEM fp16 rows (octet-d layout, HFMA2, fp16 accum)
        __half2 hacc0 = hz, hacc1 = hz, hacc2 = hz, hacc3 = hz;
        {
            const int rb = w * 84 + jway;          // local row in sW16
            #pragma unroll
            for (int it = 0; it < 21; it++) {
                const int r = rb + it * 4;
                const __half2 hj = sHd[CBASE + r];
                const uint4 wv = ((const uint4*)sW16)[r * 8 + oct];
                hacc0 = __hfma2(u2h(wv.x), hj, hacc0);
                hacc1 = __hfma2(u2h(wv.y), hj, hacc1);
                hacc2 = __hfma2(u2h(wv.z), hj, hacc2);
                hacc3 = __hfma2(u2h(wv.w), hj, hacc3);
            }
        }
        // streamed rows
        {
            const int jb = XBASE + w * 24 + jway;
            #pragma unroll
            for (int it = 0; it < 6; it++) {
                const __half2 hj = sHd[jb + it * 4];
                hacc0 = __hfma2(u2h(xv[it].x), hj, hacc0);
                hacc1 = __hfma2(u2h(xv[it].y), hj, hacc1);
                hacc2 = __hfma2(u2h(xv[it].z), hj, hacc2);
                hacc3 = __hfma2(u2h(xv[it].w), hj, hacc3);
            }
        }

        // reduce quad-layout partials (reg path): h16 pairs
        {
            float2 f0 = upk2(qa0), f1 = upk2(qa1), f2 = upk2(qa2), f3 = upk2(qa3);
            float4 s4;
            s4.x = f0.x + f2.x; s4.y = f0.y + f2.y;
            s4.z = f1.x + f3.x; s4.w = f1.y + f3.y;
            s4.x += __shfl_xor_sync(0xffffffffu, s4.x, 16);
            s4.y += __shfl_xor_sync(0xffffffffu, s4.y, 16);
            s4.z += __shfl_xor_sync(0xffffffffu, s4.z, 16);
            s4.w += __shfl_xor_sync(0xffffffffu, s4.w, 16);
            if (h16 == 0) *(float4*)(sP1 + w * 64 + q15 * 4) = s4;
        }
        // reduce octet-layout partials across jways (packed half2 shfl+hadd2)
        {
            #pragma unroll
            for (int off = 8; off <= 16; off <<= 1) {
                hacc0 = __hadd2(hacc0, u2h(__shfl_xor_sync(0xffffffffu, h2u(hacc0), off)));
                hacc1 = __hadd2(hacc1, u2h(__shfl_xor_sync(0xffffffffu, h2u(hacc1), off)));
                hacc2 = __hadd2(hacc2, u2h(__shfl_xor_sync(0xffffffffu, h2u(hacc2), off)));
                hacc3 = __hadd2(hacc3, u2h(__shfl_xor_sync(0xffffffffu, h2u(hacc3), off)));
            }
            if (jway == 0) {
                const float2 f0 = __half22float2(hacc0);
                const float2 f1 = __half22float2(hacc1);
                const float2 f2 = __half22float2(hacc2);
                const float2 f3 = __half22float2(hacc3);
                *(float4*)(sP2 + w * 64 + oct * 8)     = make_float4(f0.x, f0.y, f1.x, f1.y);
                *(float4*)(sP2 + w * 64 + oct * 8 + 4) = make_float4(f2.x, f2.y, f3.x, f3.y);
            }
        }
        __syncthreads();

        // ---- stage 2 (tid<64): reduce partials -> sigmoid gate ----
        if (tid < 64) {
            float s = sGr[c * 64 + tid];
            #pragma unroll
            for (int ww = 0; ww < 16; ww++)
                s += sP1[ww * 64 + tid] + sP2[ww * 64 + tid];
            sG[tid] = __fdividef(1.f, 1.f + __expf(-s));
        }

        // ---- geometric product (g-independent): n = A_c @ h[dB] ----
        unsigned long long n0 = 0ull, n1 = 0ull;
        {
            const float* hrow = hc + dB * 32;
            const ulonglong2* Ap = (const ulonglong2*)(sA + c * 1024) + (tid & 7);
            #pragma unroll
            for (int jq = 0; jq < 8; jq++) {
                const float4 hv = *(const float4*)(hrow + jq * 4);
                unsigned long long hp;
                ulonglong2 av;
                hp = pk2(hv.x, hv.x); av = Ap[(jq * 4 + 0) * 8];
                ffma2(n0, av.x, hp); ffma2(n1, av.y, hp);
                hp = pk2(hv.y, hv.y); av = Ap[(jq * 4 + 1) * 8];
                ffma2(n0, av.x, hp); ffma2(n1, av.y, hp);
                hp = pk2(hv.z, hv.z); av = Ap[(jq * 4 + 2) * 8];
                ffma2(n0, av.x, hp); ffma2(n1, av.y, hp);
                hp = pk2(hv.w, hv.w); av = Ap[(jq * 4 + 3) * 8];
                ffma2(n0, av.x, hp); ffma2(n1, av.y, hp);
            }
        }
        __syncthreads();

        // ---- blend + normalize + store (fp32 + dup-half2) ----
        {
            const float g  = sG[dB];
            const float om = 1.f - g;
            const float4 hq = *(const float4*)(hc + dB * 32 + k0);
            const float2 na = upk2(n0);
            const float2 nb = upk2(n1);
            float4 v;
            v.x = om * hq.x + g * na.x;
            v.y = om * hq.y + g * na.y;
            v.z = om * hq.z + g * nb.x;
            v.w = om * hq.w + g * nb.y;
            float ss = v.x * v.x + v.y * v.y + v.z * v.z + v.w * v.w;
            ss += __shfl_xor_sync(0xffffffffu, ss, 1);
            ss += __shfl_xor_sync(0xffffffffu, ss, 2);
            ss += __shfl_xor_sync(0xffffffffu, ss, 4);
            const float sc = __fdividef(1.f, sqrtf(ss) + 1e-8f);
            v.x *= sc; v.y *= sc; v.z *= sc; v.w *= sc;
            *(float4*)(hn + dB * 32 + k0) = v;
            uint4 pd;
            pd.x = h2u(__floats2half2_rn(v.x, v.x));
            pd.y = h2u(__floats2half2_rn(v.y, v.y));
            pd.z = h2u(__floats2half2_rn(v.z, v.z));
            pd.w = h2u(__floats2half2_rn(v.w, v.w));
            *(uint4*)(sHd + dB * 32 + k0) = pd;
        }
        __syncthreads();
    }

    // ============ Head: z = h@w1.T + b1, LN, relu, @w2.T + b2 ============
    const float* hF = sH0;   // TT even -> final state in sH0
    #pragma unroll 1
    for (int rr = 0; rr < 8; rr++) {
        const int r = w * 8 + rr;
        float a = 0.f;
        #pragma unroll 4
        for (int ch = 0; ch < 16; ch++) {
            const int j = ch * 128 + lane * 4;
            const float4 hv = *(const float4*)(hF + j);
            const float4 wv = *(const float4*)(w1 + (size_t)r * 2048 + j);
            a = fmaf(wv.x, hv.x, fmaf(wv.y, hv.y,
                fmaf(wv.z, hv.z, fmaf(wv.w, hv.w, a))));
        }
        #pragma unroll
        for (int off = 16; off; off >>= 1) a += __shfl_xor_sync(0xffffffffu, a, off);
        if (lane == 0) sZ[r] = a + __ldg(b1 + r);
    }
    __syncthreads();

    if (w == 0) {
        float zv[4];
        #pragma unroll
        for (int qq = 0; qq < 4; qq++) zv[qq] = sZ[lane + 32 * qq];
        float s1 = zv[0] + zv[1] + zv[2] + zv[3];
        float s2 = zv[0] * zv[0] + zv[1] * zv[1] + zv[2] * zv[2] + zv[3] * zv[3];
        #pragma unroll
        for (int off = 16; off; off >>= 1) {
            s1 += __shfl_xor_sync(0xffffffffu, s1, off);
            s2 += __shfl_xor_sync(0xffffffffu, s2, off);
        }
        const float mu  = s1 * (1.f / 128.f);
        const float var = s2 * (1.f / 128.f) - mu * mu;
        const float rs  = __fdividef(1.f, sqrtf(var + 1e-5f));
        float o0 = 0.f, o1 = 0.f;
        #pragma unroll
        for (int qq = 0; qq < 4; qq++) {
            const int r = lane + 32 * qq;
            float zn = (zv[qq] - mu) * rs * __ldg(ln_g + r) + __ldg(ln_b + r);
            zn = fmaxf(zn, 0.f);
            o0 = fmaf(zn, __ldg(w2 + r), o0);
            o1 = fmaf(zn, __ldg(w2 + 128 + r), o1);
        }
        #pragma unroll
        for (int off = 16; off; off >>= 1) {
            o0 += __shfl_xor_sync(0xffffffffu, o0, off);
            o1 += __shfl_xor_sync(0xffffffffu, o1, off);
        }
        if (lane == 0) {
            out[b * 2 + 0] = o0 + __ldg(b2 + 0);
            out[b * 2 + 1] = o1 + __ldg(b2 + 1);
        }
    }
}

extern "C" void kernel_launch(void* const* d_in, const int* in_sizes, int n_in,
                              void* d_out, int out_size) {
    const int*   x      = (const int*)  d_in[0];
    const float* emb    = (const float*)d_in[1];
    const float* gate_w = (const float*)d_in[2];
    const float* gate_b = (const float*)d_in[3];
    const float* w1     = (const float*)d_in[4];
    const float* b1     = (const float*)d_in[5];
    const float* ln_g   = (const float*)d_in[6];
    const float* ln_b   = (const float*)d_in[7];
    const float* w2     = (const float*)d_in[8];
    const float* b2     = (const float*)d_in[9];
    const float* gp     = (const float*)d_in[10];
    float* out = (float*)d_out;

    setup_kernel<<<1, 256>>>(emb, gate_w, gate_b, gp);

    const int smem_bytes = SMEM_FLOATS * 4;
    cudaFuncSetAttribute(versor_main_kernel,
                         cudaFuncAttributeMaxDynamicSharedMemorySize, smem_bytes);
    versor_main_kernel<<<BB, NT, smem_bytes>>>(x, w1, b1, ln_g, ln_b,
                                               w2, b2, out);
}

// round 5
// speedup vs baseline: 1.5257x; 1.0012x over previous
#include <cuda_runtime.h>
#include <cuda_fp16.h>
#include <math.h>

#define BB 128
#define TT 512
#define GW_STRIDE 2080
#define NT 512

#define RROWS 320                 // fp32 rows in registers       [0,320)
#define CBASE 320                 // fp16 rows cached in SMEM     [320,1664)
#define CROWS 1344
#define XBASE 1664                // fp16 rows streamed from L2   [1664,2048)

// SMEM float offsets
#define OFF_H0 43008              // sW16 = 1344*64 halfs = 43008 floats
#define OFF_H1 45056
#define OFF_HD 47104              // duplicated half2 h (2048 half2)
#define OFF_A  49152
#define OFF_P1 53248
#define OFF_P2 54272
#define OFF_G  55296
#define OFF_GR 55360
#define OFF_X  55616
#define SMEM_FLOATS 56128         // 224512 bytes

__device__ float  d_A[4096];          // A[c][j][k]
__device__ float  d_gr[256];          // gate_b + r-term, [c][d]
__device__ float  d_gw32[2048 * 64];  // transposed fp32 weights [j][d]
__device__ __half d_gw16[2048 * 64];  // transposed fp16 weights [j][d]

static __device__ __forceinline__ unsigned long long pk2(float a, float b) {
    unsigned long long r;
    asm("mov.b64 %0, {%1,%2};" : "=l"(r) : "f"(a), "f"(b));
    return r;
}
static __device__ __forceinline__ void ffma2(unsigned long long& d,
                                             unsigned long long a,
                                             unsigned long long b) {
    asm("fma.rn.f32x2 %0, %1, %2, %0;" : "+l"(d) : "l"(a), "l"(b));
}
static __device__ __forceinline__ float2 upk2(unsigned long long v) {
    float lo, hi;
    asm("mov.b64 {%0,%1}, %2;" : "=f"(lo), "=f"(hi) : "l"(v));
    return make_float2(lo, hi);
}
static __device__ __forceinline__ unsigned h2u(__half2 h) {
    return *(unsigned*)&h;
}
static __device__ __forceinline__ __half2 u2h(unsigned u) {
    return *(__half2*)&u;
}

__global__ void setup_kernel(const float* __restrict__ emb,
                             const float* __restrict__ gate_w,
                             const float* __restrict__ gate_b,
                             const float* __restrict__ gp) {
    __shared__ float r[4][32];
    int t = threadIdx.x;           // 256 threads
    if (t < 128) {
        int c = t >> 5, i = t & 31;
        float v = emb[c * 32 + i];
        float s = v * v;
        #pragma unroll
        for (int off = 16; off; off >>= 1) s += __shfl_xor_sync(0xffffffffu, s, off);
        r[c][i] = v / (sqrtf(s) + 1e-8f);
    }
    __syncthreads();

    for (int idx = t; idx < 4096; idx += 256) {
        int cc = idx >> 10, jk = idx & 1023;
        float acc = 0.f;
        #pragma unroll
        for (int ii = 0; ii < 32; ii++) acc += r[cc][ii] * gp[ii * 1024 + jk];
        d_A[idx] = acc;
    }
    for (int idx = t; idx < 256; idx += 256) {
        int cc = idx >> 6, d = idx & 63;
        float acc = gate_b[d];
        #pragma unroll
        for (int ii = 0; ii < 32; ii++)
            acc += gate_w[d * GW_STRIDE + 2048 + ii] * r[cc][ii];
        d_gr[idx] = acc;
    }
    for (int idx = t; idx < 2048 * 64; idx += 256) {
        int j = idx >> 6, d = idx & 63;
        float v = gate_w[(size_t)d * GW_STRIDE + j];
        d_gw32[idx] = v;
        d_gw16[idx] = __float2half_rn(v);
    }
}

__global__ void __launch_bounds__(NT, 1)
versor_main_kernel(const int* __restrict__ x,
                   const float* __restrict__ w1,
                   const float* __restrict__ b1,
                   const float* __restrict__ ln_g,
                   const float* __restrict__ ln_b,
                   const float* __restrict__ w2,
                   const float* __restrict__ b2,
                   float* __restrict__ out) {
    extern __shared__ float sm[];
    __half*  sW16 = (__half*)sm;          // [1344][64] fp16 (local row idx)
    float*   sH0  = sm + OFF_H0;
    float*   sH1  = sm + OFF_H1;
    __half2* sHd  = (__half2*)(sm + OFF_HD);   // duplicated (h_j,h_j)
    float*   sA   = sm + OFF_A;
    float*   sP1  = sm + OFF_P1;          // quad-layout partials [16][64]
    float*   sP2  = sm + OFF_P2;          // octet-layout partials [16][64]
    float*   sG   = sm + OFF_G;
    float*   sGr  = sm + OFF_GR;
    int*     sX   = (int*)(sm + OFF_X);
    float*   sZ   = sP1;                  // head alias

    const int tid  = threadIdx.x;
    const int lane = tid & 31;
    const int w    = tid >> 5;            // warp 0..15
    const int h16  = lane >> 4;
    const int q15  = lane & 15;
    const int jway = lane >> 3;           // 0..3
    const int oct  = lane & 7;            // d-octet
    const int b    = blockIdx.x;

    // ---- init SMEM ----
    for (int idx = tid; idx < CROWS * 8; idx += NT)      // 1344*64 halfs as uint4
        ((uint4*)sW16)[idx] = ((const uint4*)(d_gw16 + CBASE * 64))[idx];
    for (int idx = tid; idx < 4096; idx += NT) sA[idx] = d_A[idx];
    for (int idx = tid; idx < 256;  idx += NT) sGr[idx] = d_gr[idx];
    for (int idx = tid; idx < 2048; idx += NT) {
        const float v = ((idx & 31) == 0) ? 1.f : 0.f;
        sH0[idx] = v;
        sHd[idx] = __floats2half2_rn(v, v);
    }
    for (int idx = tid; idx < TT; idx += NT) sX[idx] = x[b * TT + idx];

    // ---- register-resident fp32 weights: rows [0,320), 10 j x 4 d/thread ----
    unsigned long long wpk[20];
    {
        const int jb = w * 20 + h16 * 10;
        #pragma unroll
        for (int jj = 0; jj < 10; jj++) {
            const float4 v = *(const float4*)(d_gw32 + (size_t)(jb + jj) * 64 + q15 * 4);
            wpk[2 * jj]     = pk2(v.x, v.y);
            wpk[2 * jj + 1] = pk2(v.z, v.w);
        }
    }
    __syncthreads();

    const int dB = tid >> 3;              // phase-B versor
    const int k0 = (tid & 7) * 4;         // phase-B blade quad
    const __half2 hz = __float2half2_rn(0.f);

    #pragma unroll 1
    for (int t = 0; t < TT; t++) {
        float* hc = (t & 1) ? sH1 : sH0;
        float* hn = (t & 1) ? sH0 : sH1;
        const int c = sX[t];

        // ============ Phase A: gate partial dots ============
        // prefetch streamed fp16 rows (L2)
        uint4 xv[6];
        {
            const int rb = XBASE + w * 24 + jway;
            const uint4* g16 = (const uint4*)d_gw16;
            #pragma unroll
            for (int it = 0; it < 6; it++)
                xv[it] = __ldg(g16 + (rb + it * 4) * 8 + oct);
        }

        // register fp32 rows (quad-d layout, f32x2)
        unsigned long long qa0 = 0ull, qa1 = 0ull, qa2 = 0ull, qa3 = 0ull;
        {
            const int jb = w * 20 + h16 * 10;
            #pragma unroll
            for (int jj = 0; jj < 10; jj += 2) {
                const float hj0 = hc[jb + jj];
                const unsigned long long hp0 = pk2(hj0, hj0);
                ffma2(qa0, wpk[2 * jj],     hp0);
                ffma2(qa1, wpk[2 * jj + 1], hp0);
                const float hj1 = hc[jb + jj + 1];
                const unsigned long long hp1 = pk2(hj1, hj1);
                ffma2(qa2, wpk[2 * jj + 2], hp1);
                ffma2(qa3, wpk[2 * jj + 3], hp1);
            }
        }

        // SMEM fp16 rows (octet-d layout, HFMA2, fp16 accum)
        __half2 hacc0 = hz, hacc1 = hz, hacc2 = hz, hacc3 = hz;
        {
            const int rb = w * 84 + jway;          // local row in sW16
            #pragma unroll
            for (int it = 0; it < 21; it++) {
                const int r = rb + it * 4;
                const __half2 hj = sHd[CBASE + r];
                const uint4 wv = ((const uint4*)sW16)[r * 8 + oct];
                hacc0 = __hfma2(u2h(wv.x), hj, hacc0);
                hacc1 = __hfma2(u2h(wv.y), hj, hacc1);
                hacc2 = __hfma2(u2h(wv.z), hj, hacc2);
                hacc3 = __hfma2(u2h(wv.w), hj, hacc3);
            }
        }
        // streamed rows
        {
            const int jb = XBASE + w * 24 + jway;
            #pragma unroll
            for (int it = 0; it < 6; it++) {
                const __half2 hj = sHd[jb + it * 4];
                hacc0 = __hfma2(u2h(xv[it].x), hj, hacc0);
                hacc1 = __hfma2(u2h(xv[it].y), hj, hacc1);
                hacc2 = __hfma2(u2h(xv[it].z), hj, hacc2);
                hacc3 = __hfma2(u2h(xv[it].w), hj, hacc3);
            }
        }

        // reduce quad-layout partials (reg path): h16 pairs
        {
            float2 f0 = upk2(qa0), f1 = upk2(qa1), f2 = upk2(qa2), f3 = upk2(qa3);
            float4 s4;
            s4.x = f0.x + f2.x; s4.y = f0.y + f2.y;
            s4.z = f1.x + f3.x; s4.w = f1.y + f3.y;
            s4.x += __shfl_xor_sync(0xffffffffu, s4.x, 16);
            s4.y += __shfl_xor_sync(0xffffffffu, s4.y, 16);
            s4.z += __shfl_xor_sync(0xffffffffu, s4.z, 16);
            s4.w += __shfl_xor_sync(0xffffffffu, s4.w, 16);
            if (h16 == 0) *(float4*)(sP1 + w * 64 + q15 * 4) = s4;
        }
        // reduce octet-layout partials across jways (packed half2 shfl+hadd2)
        {
            #pragma unroll
            for (int off = 8; off <= 16; off <<= 1) {
                hacc0 = __hadd2(hacc0, u2h(__shfl_xor_sync(0xffffffffu, h2u(hacc0), off)));
                hacc1 = __hadd2(hacc1, u2h(__shfl_xor_sync(0xffffffffu, h2u(hacc1), off)));
                hacc2 = __hadd2(hacc2, u2h(__shfl_xor_sync(0xffffffffu, h2u(hacc2), off)));
                hacc3 = __hadd2(hacc3, u2h(__shfl_xor_sync(0xffffffffu, h2u(hacc3), off)));
            }
            if (jway == 0) {
                const float2 f0 = __half22float2(hacc0);
                const float2 f1 = __half22float2(hacc1);
                const float2 f2 = __half22float2(hacc2);
                const float2 f3 = __half22float2(hacc3);
                *(float4*)(sP2 + w * 64 + oct * 8)     = make_float4(f0.x, f0.y, f1.x, f1.y);
                *(float4*)(sP2 + w * 64 + oct * 8 + 4) = make_float4(f2.x, f2.y, f3.x, f3.y);
            }
        }
        __syncthreads();

        // ---- stage 2 (tid<64): reduce partials -> sigmoid gate ----
        if (tid < 64) {
            float s = sGr[c * 64 + tid];
            #pragma unroll
            for (int ww = 0; ww < 16; ww++)
                s += sP1[ww * 64 + tid] + sP2[ww * 64 + tid];
            sG[tid] = __fdividef(1.f, 1.f + __expf(-s));
        }

        // ---- geometric product (g-independent): n = A_c @ h[dB] ----
        unsigned long long n0 = 0ull, n1 = 0ull;
        {
            const float* hrow = hc + dB * 32;
            const ulonglong2* Ap = (const ulonglong2*)(sA + c * 1024) + (tid & 7);
            #pragma unroll
            for (int jq = 0; jq < 8; jq++) {
                const float4 hv = *(const float4*)(hrow + jq * 4);
                unsigned long long hp;
                ulonglong2 av;
                hp = pk2(hv.x, hv.x); av = Ap[(jq * 4 + 0) * 8];
                ffma2(n0, av.x, hp); ffma2(n1, av.y, hp);
                hp = pk2(hv.y, hv.y); av = Ap[(jq * 4 + 1) * 8];
                ffma2(n0, av.x, hp); ffma2(n1, av.y, hp);
                hp = pk2(hv.z, hv.z); av = Ap[(jq * 4 + 2) * 8];
                ffma2(n0, av.x, hp); ffma2(n1, av.y, hp);
                hp = pk2(hv.w, hv.w); av = Ap[(jq * 4 + 3) * 8];
                ffma2(n0, av.x, hp); ffma2(n1, av.y, hp);
            }
        }
        __syncthreads();

        // ---- blend + normalize + store (fp32 + dup-half2) ----
        {
            const float g  = sG[dB];
            const float om = 1.f - g;
            const float4 hq = *(const float4*)(hc + dB * 32 + k0);
            const float2 na = upk2(n0);
            const float2 nb = upk2(n1);
            float4 v;
            v.x = om * hq.x + g * na.x;
            v.y = om * hq.y + g * na.y;
            v.z = om * hq.z + g * nb.x;
            v.w = om * hq.w + g * nb.y;
            float ss = v.x * v.x + v.y * v.y + v.z * v.z + v.w * v.w;
            ss += __shfl_xor_sync(0xffffffffu, ss, 1);
            ss += __shfl_xor_sync(0xffffffffu, ss, 2);
            ss += __shfl_xor_sync(0xffffffffu, ss, 4);
            const float sc = __fdividef(1.f, sqrtf(ss) + 1e-8f);
            v.x *= sc; v.y *= sc; v.z *= sc; v.w *= sc;
            *(float4*)(hn + dB * 32 + k0) = v;
            uint4 pd;
            pd.x = h2u(__floats2half2_rn(v.x, v.x));
            pd.y = h2u(__floats2half2_rn(v.y, v.y));
            pd.z = h2u(__floats2half2_rn(v.z, v.z));
            pd.w = h2u(__floats2half2_rn(v.w, v.w));
            *(uint4*)(sHd + dB * 32 + k0) = pd;
        }
        __syncthreads();
    }

    // ============ Head: z = h@w1.T + b1, LN, relu, @w2.T + b2 ============
    const float* hF = sH0;   // TT even -> final state in sH0
    #pragma unroll 1
    for (int rr = 0; rr < 8; rr++) {
        const int r = w * 8 + rr;
        float a = 0.f;
        #pragma unroll 4
        for (int ch = 0; ch < 16; ch++) {
            const int j = ch * 128 + lane * 4;
            const float4 hv = *(const float4*)(hF + j);
            const float4 wv = *(const float4*)(w1 + (size_t)r * 2048 + j);
            a = fmaf(wv.x, hv.x, fmaf(wv.y, hv.y,
                fmaf(wv.z, hv.z, fmaf(wv.w, hv.w, a))));
        }
        #pragma unroll
        for (int off = 16; off; off >>= 1) a += __shfl_xor_sync(0xffffffffu, a, off);
        if (lane == 0) sZ[r] = a + __ldg(b1 + r);
    }
    __syncthreads();

    if (w == 0) {
        float zv[4];
        #pragma unroll
        for (int qq = 0; qq < 4; qq++) zv[qq] = sZ[lane + 32 * qq];
        float s1 = zv[0] + zv[1] + zv[2] + zv[3];
        float s2 = zv[0] * zv[0] + zv[1] * zv[1] + zv[2] * zv[2] + zv[3] * zv[3];
        #pragma unroll
        for (int off = 16; off; off >>= 1) {
            s1 += __shfl_xor_sync(0xffffffffu, s1, off);
            s2 += __shfl_xor_sync(0xffffffffu, s2, off);
        }
        const float mu  = s1 * (1.f / 128.f);
        const float var = s2 * (1.f / 128.f) - mu * mu;
        const float rs  = __fdividef(1.f, sqrtf(var + 1e-5f));
        float o0 = 0.f, o1 = 0.f;
        #pragma unroll
        for (int qq = 0; qq < 4; qq++) {
            const int r = lane + 32 * qq;
            float zn = (zv[qq] - mu) * rs * __ldg(ln_g + r) + __ldg(ln_b + r);
            zn = fmaxf(zn, 0.f);
            o0 = fmaf(zn, __ldg(w2 + r), o0);
            o1 = fmaf(zn, __ldg(w2 + 128 + r), o1);
        }
        #pragma unroll
        for (int off = 16; off; off >>= 1) {
            o0 += __shfl_xor_sync(0xffffffffu, o0, off);
            o1 += __shfl_xor_sync(0xffffffffu, o1, off);
        }
        if (lane == 0) {
            out[b * 2 + 0] = o0 + __ldg(b2 + 0);
            out[b * 2 + 1] = o1 + __ldg(b2 + 1);
        }
    }
}

extern "C" void kernel_launch(void* const* d_in, const int* in_sizes, int n_in,
                              void* d_out, int out_size) {
    const int*   x      = (const int*)  d_in[0];
    const float* emb    = (const float*)d_in[1];
    const float* gate_w = (const float*)d_in[2];
    const float* gate_b = (const float*)d_in[3];
    const float* w1     = (const float*)d_in[4];
    const float* b1     = (const float*)d_in[5];
    const float* ln_g   = (const float*)d_in[6];
    const float* ln_b   = (const float*)d_in[7];
    const float* w2     = (const float*)d_in[8];
    const float* b2     = (const float*)d_in[9];
    const float* gp     = (const float*)d_in[10];
    float* out = (float*)d_out;

    setup_kernel<<<1, 256>>>(emb, gate_w, gate_b, gp);

    const int smem_bytes = SMEM_FLOATS * 4;
    cudaFuncSetAttribute(versor_main_kernel,
                         cudaFuncAttributeMaxDynamicSharedMemorySize, smem_bytes);
    versor_main_kernel<<<BB, NT, smem_bytes>>>(x, w1, b1, ln_g, ln_b,
                                               w2, b2, out);
}

// round 9
// speedup vs baseline: 1.7190x; 1.1267x over previous
#include <cuda_runtime.h>
#include <cuda_fp16.h>
#include <math.h>

#define BB 128
#define TT 512
#define GW_STRIDE 2080
#define NT 512

// gate row partition: [0,640) registers fp16, [640,1600) SMEM fp16, [1600,2048) L2/L1D stream
#define RROWS 640
#define SBASE 640
#define SROWS 960
#define XBASE 1600

// SMEM float offsets (sW16 = 960*64 halves = 61440 halves = 30720 floats)
#define OFF_H0 30720
#define OFF_H1 32768
#define OFF_HD 34816              // duplicated half2 h [2048] = 2048 floats
#define OFF_A  36864              // 4x32x32 fp32
#define OFF_P  40960              // partials [16][68] padded
#define OFF_GR 42048              // 4x64
#define OFF_X  42304              // 512 ints
#define SMEM_FLOATS 42816         // 171264 bytes

__device__ float  d_A[4096];          // A[c][j][k]
__device__ float  d_gr[256];          // gate_b + r-term, [c][d]
__device__ __half d_gw16[2048 * 64];  // transposed fp16 weights [j][d]

static __device__ __forceinline__ unsigned long long pk2(float a, float b) {
    unsigned long long r; asm("mov.b64 %0, {%1,%2};" : "=l"(r) : "f"(a), "f"(b)); return r;
}
static __device__ __forceinline__ void ffma2(unsigned long long& d,
                                             unsigned long long a, unsigned long long b) {
    asm("fma.rn.f32x2 %0, %1, %2, %0;" : "+l"(d) : "l"(a), "l"(b));
}
static __device__ __forceinline__ float2 upk2(unsigned long long v) {
    float lo, hi; asm("mov.b64 {%0,%1}, %2;" : "=f"(lo), "=f"(hi) : "l"(v));
    return make_float2(lo, hi);
}
static __device__ __forceinline__ unsigned h2u(__half2 h) { return *(unsigned*)&h; }
static __device__ __forceinline__ __half2 u2h(unsigned u) { return *(__half2*)&u; }

__global__ void setup_kernel(const float* __restrict__ emb,
                             const float* __restrict__ gate_w,
                             const float* __restrict__ gate_b,
                             const float* __restrict__ gp) {
    __shared__ float r[4][32];
    int t = threadIdx.x;           // 256 threads
    if (t < 128) {
        int c = t >> 5, i = t & 31;
        float v = emb[c * 32 + i];
        float s = v * v;
        #pragma unroll
        for (int off = 16; off; off >>= 1) s += __shfl_xor_sync(0xffffffffu, s, off);
        r[c][i] = v / (sqrtf(s) + 1e-8f);
    }
    __syncthreads();
    for (int idx = t; idx < 4096; idx += 256) {
        int cc = idx >> 10, jk = idx & 1023;
        float acc = 0.f;
        #pragma unroll
        for (int ii = 0; ii < 32; ii++) acc += r[cc][ii] * gp[ii * 1024 + jk];
        d_A[idx] = acc;
    }
    for (int idx = t; idx < 256; idx += 256) {
        int cc = idx >> 6, d = idx & 63;
        float acc = gate_b[d];
        #pragma unroll
        for (int ii = 0; ii < 32; ii++)
            acc += gate_w[d * GW_STRIDE + 2048 + ii] * r[cc][ii];
        d_gr[idx] = acc;
    }
    for (int idx = t; idx < 2048 * 64; idx += 256) {
        int j = idx >> 6, d = idx & 63;
        d_gw16[idx] = __float2half_rn(gate_w[(size_t)d * GW_STRIDE + j]);
    }
}

__global__ void __launch_bounds__(NT, 1)
versor_main_kernel(const int* __restrict__ x,
                   const float* __restrict__ w1, const float* __restrict__ b1,
                   const float* __restrict__ ln_g, const float* __restrict__ ln_b,
                   const float* __restrict__ w2, const float* __restrict__ b2,
                   float* __restrict__ out) {
    extern __shared__ float sm[];
    __half*  sW16 = (__half*)sm;              // [960][64] fp16 (local row = j-640)
    float*   sH0  = sm + OFF_H0;
    float*   sH1  = sm + OFF_H1;
    __half2* sHd  = (__half2*)(sm + OFF_HD);  // duplicated (h,h), all 2048 rows
    float*   sA   = sm + OFF_A;
    float*   sP   = sm + OFF_P;               // [16][68]
    float*   sGr  = sm + OFF_GR;
    int*     sX   = (int*)(sm + OFF_X);
    float*   sZ   = sP;                       // head alias

    const int tid  = threadIdx.x;
    const int lane = tid & 31;
    const int w    = tid >> 5;                // warp 0..15
    const int jway = lane >> 3;               // 0..3
    const int oct  = lane & 7;                // d-octet
    const int b    = blockIdx.x;

    // ---- init SMEM ----
    for (int idx = tid; idx < SROWS * 8; idx += NT)   // 960*64 halves as uint4
        ((uint4*)sW16)[idx] = ((const uint4*)(d_gw16 + SBASE * 64))[idx];
    for (int idx = tid; idx < 4096; idx += NT) sA[idx] = d_A[idx];
    for (int idx = tid; idx < 256;  idx += NT) sGr[idx] = d_gr[idx];
    for (int idx = tid; idx < TT;   idx += NT) sX[idx] = x[b * TT + idx];
    for (int idx = tid; idx < 2048; idx += NT) {
        const float v = ((idx & 31) == 0) ? 1.f : 0.f;
        sH0[idx] = v;
        sHd[idx] = __floats2half2_rn(v, v);
    }

    // ---- register fp16 weights: rows [0,640), 10 j x 8 d(4 half2)/thread ----
    unsigned wreg[40];
    {
        const int jb = w * 40 + jway * 10;
        #pragma unroll
        for (int jj = 0; jj < 10; jj++) {
            const uint4 v = *(const uint4*)(d_gw16 + (size_t)(jb + jj) * 64 + oct * 8);
            wreg[4 * jj + 0] = v.x; wreg[4 * jj + 1] = v.y;
            wreg[4 * jj + 2] = v.z; wreg[4 * jj + 3] = v.w;
        }
    }
    __syncthreads();

    const int dB = tid >> 3;              // phase-B versor
    const int s8 = tid & 7;               // 8-thread subgroup within versor
    const int k0 = s8 * 4;                // phase-B blade quad
    const int jg = dB * 32 + k0;
    const __half2 hz = __float2half2_rn(0.f);

    #pragma unroll 1
    for (int t = 0; t < TT; t++) {
        float* hc = (t & 1) ? sH1 : sH0;
        float* hn = (t & 1) ? sH0 : sH1;
        const int c = sX[t];

        // ============ Phase A: gate partial dots (all HFMA2, octet-d) ============
        // prefetch streamed rows (L2/L1D)
        uint4 xv[7];
        {
            const int j0 = XBASE + w * 28 + jway;
            #pragma unroll
            for (int it = 0; it < 7; it++)
                xv[it] = __ldg((const uint4*)d_gw16 + (j0 + it * 4) * 8 + oct);
        }
        __half2 ha0 = hz, ha1 = hz, ha2 = hz, ha3 = hz;
        // register rows
        {
            const int jb = w * 40 + jway * 10;
            #pragma unroll
            for (int jj = 0; jj < 10; jj++) {
                const __half2 hj = sHd[jb + jj];
                ha0 = __hfma2(u2h(wreg[4 * jj + 0]), hj, ha0);
                ha1 = __hfma2(u2h(wreg[4 * jj + 1]), hj, ha1);
                ha2 = __hfma2(u2h(wreg[4 * jj + 2]), hj, ha2);
                ha3 = __hfma2(u2h(wreg[4 * jj + 3]), hj, ha3);
            }
        }
        // SMEM rows
        {
            const int rb = w * 60 + jway * 15;
            #pragma unroll
            for (int i = 0; i < 15; i++) {
                const int r = rb + i;
                const __half2 hj = sHd[SBASE + r];
                const uint4 wv = ((const uint4*)sW16)[r * 8 + oct];
                ha0 = __hfma2(u2h(wv.x), hj, ha0);
                ha1 = __hfma2(u2h(wv.y), hj, ha1);
                ha2 = __hfma2(u2h(wv.z), hj, ha2);
                ha3 = __hfma2(u2h(wv.w), hj, ha3);
            }
        }
        // streamed rows
        {
            const int j0 = XBASE + w * 28 + jway;
            #pragma unroll
            for (int it = 0; it < 7; it++) {
                const __half2 hj = sHd[j0 + it * 4];
                ha0 = __hfma2(u2h(xv[it].x), hj, ha0);
                ha1 = __hfma2(u2h(xv[it].y), hj, ha1);
                ha2 = __hfma2(u2h(xv[it].z), hj, ha2);
                ha3 = __hfma2(u2h(xv[it].w), hj, ha3);
            }
        }
        // reduce across the 4 jways (lane bits 3,4), store fp32 partials
        {
            #pragma unroll
            for (int off = 8; off <= 16; off <<= 1) {
                ha0 = __hadd2(ha0, u2h(__shfl_xor_sync(0xffffffffu, h2u(ha0), off)));
                ha1 = __hadd2(ha1, u2h(__shfl_xor_sync(0xffffffffu, h2u(ha1), off)));
                ha2 = __hadd2(ha2, u2h(__shfl_xor_sync(0xffffffffu, h2u(ha2), off)));
                ha3 = __hadd2(ha3, u2h(__shfl_xor_sync(0xffffffffu, h2u(ha3), off)));
            }
            if (jway == 0) {
                const float2 f0 = __half22float2(ha0), f1 = __half22float2(ha1);
                const float2 f2 = __half22float2(ha2), f3 = __half22float2(ha3);
                *(float4*)(sP + w * 68 + oct * 8)     = make_float4(f0.x, f0.y, f1.x, f1.y);
                *(float4*)(sP + w * 68 + oct * 8 + 4) = make_float4(f2.x, f2.y, f3.x, f3.y);
            }
        }
        __syncthreads();   // barrier 1: partials visible, phase-A reads of sHd done

        // ---- distributed gate reduce: 8 threads per versor ----
        float g;
        {
            float s = sP[(2 * s8) * 68 + dB] + sP[(2 * s8 + 1) * 68 + dB];
            s += __shfl_xor_sync(0xffffffffu, s, 1);
            s += __shfl_xor_sync(0xffffffffu, s, 2);
            s += __shfl_xor_sync(0xffffffffu, s, 4);
            s += sGr[c * 64 + dB];
            g = __fdividef(1.f, 1.f + __expf(-s));
        }

        // ---- geometric product: n = A_c @ h[dB] ----
        unsigned long long n0 = 0ull, n1 = 0ull;
        {
            const float* hrow = hc + dB * 32;
            const ulonglong2* Ap = (const ulonglong2*)(sA + c * 1024) + s8;
            #pragma unroll
            for (int jq = 0; jq < 8; jq++) {
                const float4 hv = *(const float4*)(hrow + jq * 4);
                unsigned long long hp; ulonglong2 av;
                hp = pk2(hv.x, hv.x); av = Ap[(jq * 4 + 0) * 8];
                ffma2(n0, av.x, hp); ffma2(n1, av.y, hp);
                hp = pk2(hv.y, hv.y); av = Ap[(jq * 4 + 1) * 8];
                ffma2(n0, av.x, hp); ffma2(n1, av.y, hp);
                hp = pk2(hv.z, hv.z); av = Ap[(jq * 4 + 2) * 8];
                ffma2(n0, av.x, hp); ffma2(n1, av.y, hp);
                hp = pk2(hv.w, hv.w); av = Ap[(jq * 4 + 3) * 8];
                ffma2(n0, av.x, hp); ffma2(n1, av.y, hp);
            }
        }

        // ---- blend + normalize + store (fp32 state + dup-half2) ----
        {
            const float om = 1.f - g;
            const float4 hq = *(const float4*)(hc + dB * 32 + k0);
            const float2 na = upk2(n0);
            const float2 nb = upk2(n1);
            float4 v;
            v.x = om * hq.x + g * na.x;
            v.y = om * hq.y + g * na.y;
            v.z = om * hq.z + g * nb.x;
            v.w = om * hq.w + g * nb.y;
            float ss = v.x * v.x + v.y * v.y + v.z * v.z + v.w * v.w;
            ss += __shfl_xor_sync(0xffffffffu, ss, 1);
            ss += __shfl_xor_sync(0xffffffffu, ss, 2);
            ss += __shfl_xor_sync(0xffffffffu, ss, 4);
            const float sc = __fdividef(1.f, sqrtf(ss) + 1e-8f);
            v.x *= sc; v.y *= sc; v.z *= sc; v.w *= sc;
            *(float4*)(hn + jg) = v;
            uint4 pd;
            pd.x = h2u(__floats2half2_rn(v.x, v.x));
            pd.y = h2u(__floats2half2_rn(v.y, v.y));
            pd.z = h2u(__floats2half2_rn(v.z, v.z));
            pd.w = h2u(__floats2half2_rn(v.w, v.w));
            *(uint4*)(sHd + jg) = pd;
        }
        __syncthreads();   // barrier 2: new h (fp32 + dup) visible
    }

    // ============ Head: z = h@w1.T + b1, LN, relu, @w2.T + b2 ============
    const float* hF = sH0;   // TT even
    #pragma unroll 1
    for (int rr = 0; rr < 8; rr++) {
        const int r = w * 8 + rr;
        float a = 0.f;
        #pragma unroll 4
        for (int ch = 0; ch < 16; ch++) {
            const int j = ch * 128 + lane * 4;
            const float4 hv = *(const float4*)(hF + j);
            const float4 wv = *(const float4*)(w1 + (size_t)r * 2048 + j);
            a = fmaf(wv.x, hv.x, fmaf(wv.y, hv.y,
                fmaf(wv.z, hv.z, fmaf(wv.w, hv.w, a))));
        }
        #pragma unroll
        for (int off = 16; off; off >>= 1) a += __shfl_xor_sync(0xffffffffu, a, off);
        if (lane == 0) sZ[r] = a + __ldg(b1 + r);
    }
    __syncthreads();
    if (w == 0) {
        float zv[4];
        #pragma unroll
        for (int qq = 0; qq < 4; qq++) zv[qq] = sZ[lane + 32 * qq];
        float s1 = zv[0] + zv[1] + zv[2] + zv[3];
        float s2 = zv[0] * zv[0] + zv[1] * zv[1] + zv[2] * zv[2] + zv[3] * zv[3];
        #pragma unroll
        for (int off = 16; off; off >>= 1) {
            s1 += __shfl_xor_sync(0xffffffffu, s1, off);
            s2 += __shfl_xor_sync(0xffffffffu, s2, off);
        }
        const float mu  = s1 * (1.f / 128.f);
        const float var = s2 * (1.f / 128.f) - mu * mu;
        const float rs  = __fdividef(1.f, sqrtf(var + 1e-5f));
        float o0 = 0.f, o1 = 0.f;
        #pragma unroll
        for (int qq = 0; qq < 4; qq++) {
            const int r = lane + 32 * qq;
            float zn = (zv[qq] - mu) * rs * __ldg(ln_g + r) + __ldg(ln_b + r);
            zn = fmaxf(zn, 0.f);
            o0 = fmaf(zn, __ldg(w2 + r), o0);
            o1 = fmaf(zn, __ldg(w2 + 128 + r), o1);
        }
        #pragma unroll
        for (int off = 16; off; off >>= 1) {
            o0 += __shfl_xor_sync(0xffffffffu, o0, off);
            o1 += __shfl_xor_sync(0xffffffffu, o1, off);
        }
        if (lane == 0) {
            out[b * 2 + 0] = o0 + __ldg(b2 + 0);
            out[b * 2 + 1] = o1 + __ldg(b2 + 1);
        }
    }
}

extern "C" void kernel_launch(void* const* d_in, const int* in_sizes, int n_in,
                              void* d_out, int out_size) {
    const int*   x      = (const int*)  d_in[0];
    const float* emb    = (const float*)d_in[1];
    const float* gate_w = (const float*)d_in[2];
    const float* gate_b = (const float*)d_in[3];
    const float* w1     = (const float*)d_in[4];
    const float* b1     = (const float*)d_in[5];
    const float* ln_g   = (const float*)d_in[6];
    const float* ln_b   = (const float*)d_in[7];
    const float* w2     = (const float*)d_in[8];
    const float* b2     = (const float*)d_in[9];
    const float* gp     = (const float*)d_in[10];
    float* out = (float*)d_out;

    setup_kernel<<<1, 256>>>(emb, gate_w, gate_b, gp);

    const int smem_bytes = SMEM_FLOATS * 4;
    cudaFuncSetAttribute(versor_main_kernel,
                         cudaFuncAttributeMaxDynamicSharedMemorySize, smem_bytes);
    versor_main_kernel<<<BB, NT, smem_bytes>>>(x, w1, b1, ln_g, ln_b, w2, b2, out);
}

// round 10
// speedup vs baseline: 1.8506x; 1.0766x over previous
#include <cuda_runtime.h>
#include <cuda_fp16.h>
#include <math.h>

#define BB 128
#define TT 512
#define GW_STRIDE 2080
#define NT 512

// gate row partition: [0,768) registers fp16, [768,1536) SMEM fp16, [1536,2048) L2/L1D stream
#define RROWS 768
#define SBASE 768
#define SROWS 768
#define XBASE 1536

// SMEM float offsets (sW16 = 768*64 halves = 24576 floats)
#define OFF_H0 24576
#define OFF_H1 26624
#define OFF_HD 28672              // duplicated half2 h [2048]
#define OFF_A  30720              // 4x32x32 fp32
#define OFF_P  34816              // partials [16][68]
#define OFF_GR 35904              // 4x64
#define OFF_X  36160              // 512 ints
#define SMEM_FLOATS 36672         // 146688 bytes

__device__ float  d_A[4096];          // A[c][j][k]
__device__ float  d_gr[256];          // gate_b + r-term, [c][d]
__device__ __half d_gw16[2048 * 64];  // transposed fp16 weights [j][d]

static __device__ __forceinline__ unsigned long long pk2(float a, float b) {
    unsigned long long r; asm("mov.b64 %0, {%1,%2};" : "=l"(r) : "f"(a), "f"(b)); return r;
}
static __device__ __forceinline__ void ffma2(unsigned long long& d,
                                             unsigned long long a, unsigned long long b) {
    asm("fma.rn.f32x2 %0, %1, %2, %0;" : "+l"(d) : "l"(a), "l"(b));
}
static __device__ __forceinline__ float2 upk2(unsigned long long v) {
    float lo, hi; asm("mov.b64 {%0,%1}, %2;" : "=f"(lo), "=f"(hi) : "l"(v));
    return make_float2(lo, hi);
}
static __device__ __forceinline__ unsigned h2u(__half2 h) { return *(unsigned*)&h; }
static __device__ __forceinline__ __half2 u2h(unsigned u) { return *(__half2*)&u; }

__global__ void setup_kernel(const float* __restrict__ emb,
                             const float* __restrict__ gate_w,
                             const float* __restrict__ gate_b,
                             const float* __restrict__ gp) {
    __shared__ float r[4][32];
    int t = threadIdx.x;           // 256 threads
    if (t < 128) {
        int c = t >> 5, i = t & 31;
        float v = emb[c * 32 + i];
        float s = v * v;
        #pragma unroll
        for (int off = 16; off; off >>= 1) s += __shfl_xor_sync(0xffffffffu, s, off);
        r[c][i] = v / (sqrtf(s) + 1e-8f);
    }
    __syncthreads();
    for (int idx = t; idx < 4096; idx += 256) {
        int cc = idx >> 10, jk = idx & 1023;
        float acc = 0.f;
        #pragma unroll
        for (int ii = 0; ii < 32; ii++) acc += r[cc][ii] * gp[ii * 1024 + jk];
        d_A[idx] = acc;
    }
    for (int idx = t; idx < 256; idx += 256) {
        int cc = idx >> 6, d = idx & 63;
        float acc = gate_b[d];
        #pragma unroll
        for (int ii = 0; ii < 32; ii++)
            acc += gate_w[d * GW_STRIDE + 2048 + ii] * r[cc][ii];
        d_gr[idx] = acc;
    }
    for (int idx = t; idx < 2048 * 64; idx += 256) {
        int j = idx >> 6, d = idx & 63;
        d_gw16[idx] = __float2half_rn(gate_w[(size_t)d * GW_STRIDE + j]);
    }
}

__global__ void __launch_bounds__(NT, 1)
versor_main_kernel(const int* __restrict__ x,
                   const float* __restrict__ w1, const float* __restrict__ b1,
                   const float* __restrict__ ln_g, const float* __restrict__ ln_b,
                   const float* __restrict__ w2, const float* __restrict__ b2,
                   float* __restrict__ out) {
    extern __shared__ float sm[];
    __half*  sW16 = (__half*)sm;              // [768][64] fp16 (local row = j-768)
    float*   sH0  = sm + OFF_H0;
    float*   sH1  = sm + OFF_H1;
    __half2* sHd  = (__half2*)(sm + OFF_HD);  // duplicated (h,h), all 2048 rows
    float*   sA   = sm + OFF_A;
    float*   sP   = sm + OFF_P;               // [16][68]
    float*   sGr  = sm + OFF_GR;
    int*     sX   = (int*)(sm + OFF_X);
    float*   sZ   = sP;                       // head alias

    const int tid  = threadIdx.x;
    const int lane = tid & 31;
    const int w    = tid >> 5;                // warp 0..15
    const int jway = lane >> 3;               // 0..3
    const int oct  = lane & 7;                // d-octet
    const int b    = blockIdx.x;
    const int grp  = w * 4 + jway;            // row group 0..63

    // ---- init SMEM ----
    for (int idx = tid; idx < SROWS * 8; idx += NT)   // 768*64 halves as uint4
        ((uint4*)sW16)[idx] = ((const uint4*)(d_gw16 + SBASE * 64))[idx];
    for (int idx = tid; idx < 4096; idx += NT) sA[idx] = d_A[idx];
    for (int idx = tid; idx < 256;  idx += NT) sGr[idx] = d_gr[idx];
    for (int idx = tid; idx < TT;   idx += NT) sX[idx] = x[b * TT + idx];
    for (int idx = tid; idx < 2048; idx += NT) {
        const float v = ((idx & 31) == 0) ? 1.f : 0.f;
        sH0[idx] = v;
        sHd[idx] = __floats2half2_rn(v, v);
    }

    // ---- register fp16 weights: rows [0,768), 12 j x 8 d(4 half2)/thread ----
    unsigned wreg[48];
    {
        const int jb = grp * 12;
        #pragma unroll
        for (int jj = 0; jj < 12; jj++) {
            const uint4 v = *(const uint4*)(d_gw16 + (size_t)(jb + jj) * 64 + oct * 8);
            wreg[4 * jj + 0] = v.x; wreg[4 * jj + 1] = v.y;
            wreg[4 * jj + 2] = v.z; wreg[4 * jj + 3] = v.w;
        }
    }
    __syncthreads();

    const int dB = tid >> 3;              // phase-B versor
    const int s8 = tid & 7;               // 8-thread subgroup within versor
    const int k0 = s8 * 4;                // phase-B blade quad
    const int jg = dB * 32 + k0;
    const __half2 hz = __float2half2_rn(0.f);

    #pragma unroll 1
    for (int t = 0; t < TT; t++) {
        float* hc = (t & 1) ? sH1 : sH0;
        float* hn = (t & 1) ? sH0 : sH1;
        const int c = sX[t];

        // ============ Phase A: gate partial dots (all HFMA2, octet-d) ============
        __half2 ha0 = hz, ha1 = hz, ha2 = hz, ha3 = hz;
        const int xb = XBASE + grp * 8;                  // streamed rows base

        // issue LDG batch A (rows xb..xb+3)
        uint4 xva0, xva1, xva2, xva3;
        {
            const uint4* g16 = (const uint4*)d_gw16;
            xva0 = __ldg(g16 + (xb + 0) * 8 + oct);
            xva1 = __ldg(g16 + (xb + 1) * 8 + oct);
            xva2 = __ldg(g16 + (xb + 2) * 8 + oct);
            xva3 = __ldg(g16 + (xb + 3) * 8 + oct);
        }
        // register rows (12), hj via 3 x LDS.128 on dup array
        {
            const int jb = grp * 12;
            #pragma unroll
            for (int q = 0; q < 3; q++) {
                const uint4 hq = *(const uint4*)(sHd + jb + 4 * q);
                const __half2 h0 = u2h(hq.x), h1 = u2h(hq.y);
                const __half2 h2 = u2h(hq.z), h3 = u2h(hq.w);
                ha0 = __hfma2(u2h(wreg[16 * q + 0]),  h0, ha0);
                ha1 = __hfma2(u2h(wreg[16 * q + 1]),  h0, ha1);
                ha2 = __hfma2(u2h(wreg[16 * q + 2]),  h0, ha2);
                ha3 = __hfma2(u2h(wreg[16 * q + 3]),  h0, ha3);
                ha0 = __hfma2(u2h(wreg[16 * q + 4]),  h1, ha0);
                ha1 = __hfma2(u2h(wreg[16 * q + 5]),  h1, ha1);
                ha2 = __hfma2(u2h(wreg[16 * q + 6]),  h1, ha2);
                ha3 = __hfma2(u2h(wreg[16 * q + 7]),  h1, ha3);
                ha0 = __hfma2(u2h(wreg[16 * q + 8]),  h2, ha0);
                ha1 = __hfma2(u2h(wreg[16 * q + 9]),  h2, ha1);
                ha2 = __hfma2(u2h(wreg[16 * q + 10]), h2, ha2);
                ha3 = __hfma2(u2h(wreg[16 * q + 11]), h2, ha3);
                ha0 = __hfma2(u2h(wreg[16 * q + 12]), h3, ha0);
                ha1 = __hfma2(u2h(wreg[16 * q + 13]), h3, ha1);
                ha2 = __hfma2(u2h(wreg[16 * q + 14]), h3, ha2);
                ha3 = __hfma2(u2h(wreg[16 * q + 15]), h3, ha3);
            }
        }
        // consume LDG batch A
        {
            const uint4 hq = *(const uint4*)(sHd + xb);
            const __half2 h0 = u2h(hq.x), h1 = u2h(hq.y);
            const __half2 h2 = u2h(hq.z), h3 = u2h(hq.w);
            ha0 = __hfma2(u2h(xva0.x), h0, ha0); ha1 = __hfma2(u2h(xva0.y), h0, ha1);
            ha2 = __hfma2(u2h(xva0.z), h0, ha2); ha3 = __hfma2(u2h(xva0.w), h0, ha3);
            ha0 = __hfma2(u2h(xva1.x), h1, ha0); ha1 = __hfma2(u2h(xva1.y), h1, ha1);
            ha2 = __hfma2(u2h(xva1.z), h1, ha2); ha3 = __hfma2(u2h(xva1.w), h1, ha3);
            ha0 = __hfma2(u2h(xva2.x), h2, ha0); ha1 = __hfma2(u2h(xva2.y), h2, ha1);
            ha2 = __hfma2(u2h(xva2.z), h2, ha2); ha3 = __hfma2(u2h(xva2.w), h2, ha3);
            ha0 = __hfma2(u2h(xva3.x), h3, ha0); ha1 = __hfma2(u2h(xva3.y), h3, ha1);
            ha2 = __hfma2(u2h(xva3.z), h3, ha2); ha3 = __hfma2(u2h(xva3.w), h3, ha3);
        }
        // issue LDG batch B (rows xb+4..xb+7)
        {
            const uint4* g16 = (const uint4*)d_gw16;
            xva0 = __ldg(g16 + (xb + 4) * 8 + oct);
            xva1 = __ldg(g16 + (xb + 5) * 8 + oct);
            xva2 = __ldg(g16 + (xb + 6) * 8 + oct);
            xva3 = __ldg(g16 + (xb + 7) * 8 + oct);
        }
        // SMEM rows (12)
        {
            const int rb = grp * 12;           // local row in sW16
            #pragma unroll
            for (int q = 0; q < 3; q++) {
                const uint4 hq = *(const uint4*)(sHd + SBASE + rb + 4 * q);
                const __half2 hh[4] = { u2h(hq.x), u2h(hq.y), u2h(hq.z), u2h(hq.w) };
                #pragma unroll
                for (int rr = 0; rr < 4; rr++) {
                    const uint4 wv = ((const uint4*)sW16)[(rb + 4 * q + rr) * 8 + oct];
                    ha0 = __hfma2(u2h(wv.x), hh[rr], ha0);
                    ha1 = __hfma2(u2h(wv.y), hh[rr], ha1);
                    ha2 = __hfma2(u2h(wv.z), hh[rr], ha2);
                    ha3 = __hfma2(u2h(wv.w), hh[rr], ha3);
                }
            }
        }
        // consume LDG batch B
        {
            const uint4 hq = *(const uint4*)(sHd + xb + 4);
            const __half2 h0 = u2h(hq.x), h1 = u2h(hq.y);
            const __half2 h2 = u2h(hq.z), h3 = u2h(hq.w);
            ha0 = __hfma2(u2h(xva0.x), h0, ha0); ha1 = __hfma2(u2h(xva0.y), h0, ha1);
            ha2 = __hfma2(u2h(xva0.z), h0, ha2); ha3 = __hfma2(u2h(xva0.w), h0, ha3);
            ha0 = __hfma2(u2h(xva1.x), h1, ha0); ha1 = __hfma2(u2h(xva1.y), h1, ha1);
            ha2 = __hfma2(u2h(xva1.z), h1, ha2); ha3 = __hfma2(u2h(xva1.w), h1, ha3);
            ha0 = __hfma2(u2h(xva2.x), h2, ha0); ha1 = __hfma2(u2h(xva2.y), h2, ha1);
            ha2 = __hfma2(u2h(xva2.z), h2, ha2); ha3 = __hfma2(u2h(xva2.w), h2, ha3);
            ha0 = __hfma2(u2h(xva3.x), h3, ha0); ha1 = __hfma2(u2h(xva3.y), h3, ha1);
            ha2 = __hfma2(u2h(xva3.z), h3, ha2); ha3 = __hfma2(u2h(xva3.w), h3, ha3);
        }
        // reduce across the 4 jways (lane bits 3,4), store fp32 partials
        {
            #pragma unroll
            for (int off = 8; off <= 16; off <<= 1) {
                ha0 = __hadd2(ha0, u2h(__shfl_xor_sync(0xffffffffu, h2u(ha0), off)));
                ha1 = __hadd2(ha1, u2h(__shfl_xor_sync(0xffffffffu, h2u(ha1), off)));
                ha2 = __hadd2(ha2, u2h(__shfl_xor_sync(0xffffffffu, h2u(ha2), off)));
                ha3 = __hadd2(ha3, u2h(__shfl_xor_sync(0xffffffffu, h2u(ha3), off)));
            }
            if (jway == 0) {
                const float2 f0 = __half22float2(ha0), f1 = __half22float2(ha1);
                const float2 f2 = __half22float2(ha2), f3 = __half22float2(ha3);
                *(float4*)(sP + w * 68 + oct * 8)     = make_float4(f0.x, f0.y, f1.x, f1.y);
                *(float4*)(sP + w * 68 + oct * 8 + 4) = make_float4(f2.x, f2.y, f3.x, f3.y);
            }
        }
        __syncthreads();   // barrier 1: partials visible, phase-A reads of sHd done

        // ---- distributed gate reduce: 8 threads per versor ----
        float g;
        {
            float s = sP[(2 * s8) * 68 + dB] + sP[(2 * s8 + 1) * 68 + dB];
            s += __shfl_xor_sync(0xffffffffu, s, 1);
            s += __shfl_xor_sync(0xffffffffu, s, 2);
            s += __shfl_xor_sync(0xffffffffu, s, 4);
            s += sGr[c * 64 + dB];
            g = __fdividef(1.f, 1.f + __expf(-s));
        }

        // ---- geometric product: n = A_c @ h[dB] ----
        unsigned long long n0 = 0ull, n1 = 0ull;
        {
            const float* hrow = hc + dB * 32;
            const ulonglong2* Ap = (const ulonglong2*)(sA + c * 1024) + s8;
            #pragma unroll
            for (int jq = 0; jq < 8; jq++) {
                const float4 hv = *(const float4*)(hrow + jq * 4);
                unsigned long long hp; ulonglong2 av;
                hp = pk2(hv.x, hv.x); av = Ap[(jq * 4 + 0) * 8];
                ffma2(n0, av.x, hp); ffma2(n1, av.y, hp);
                hp = pk2(hv.y, hv.y); av = Ap[(jq * 4 + 1) * 8];
                ffma2(n0, av.x, hp); ffma2(n1, av.y, hp);
                hp = pk2(hv.z, hv.z); av = Ap[(jq * 4 + 2) * 8];
                ffma2(n0, av.x, hp); ffma2(n1, av.y, hp);
                hp = pk2(hv.w, hv.w); av = Ap[(jq * 4 + 3) * 8];
                ffma2(n0, av.x, hp); ffma2(n1, av.y, hp);
            }
        }

        // ---- blend + normalize + store (fp32 state + dup-half2) ----
        {
            const float om = 1.f - g;
            const float4 hq = *(const float4*)(hc + dB * 32 + k0);
            const float2 na = upk2(n0);
            const float2 nb = upk2(n1);
            float4 v;
            v.x = om * hq.x + g * na.x;
            v.y = om * hq.y + g * na.y;
            v.z = om * hq.z + g * nb.x;
            v.w = om * hq.w + g * nb.y;
            float ss = v.x * v.x + v.y * v.y + v.z * v.z + v.w * v.w;
            ss += __shfl_xor_sync(0xffffffffu, ss, 1);
            ss += __shfl_xor_sync(0xffffffffu, ss, 2);
            ss += __shfl_xor_sync(0xffffffffu, ss, 4);
            const float sc = __fdividef(1.f, sqrtf(ss) + 1e-8f);
            v.x *= sc; v.y *= sc; v.z *= sc; v.w *= sc;
            *(float4*)(hn + jg) = v;
            uint4 pd;
            pd.x = h2u(__floats2half2_rn(v.x, v.x));
            pd.y = h2u(__floats2half2_rn(v.y, v.y));
            pd.z = h2u(__floats2half2_rn(v.z, v.z));
            pd.w = h2u(__floats2half2_rn(v.w, v.w));
            *(uint4*)(sHd + jg) = pd;
        }
        __syncthreads();   // barrier 2: new h (fp32 + dup) visible
    }

    // ============ Head: z = h@w1.T + b1, LN, relu, @w2.T + b2 ============
    const float* hF = sH0;   // TT even
    #pragma unroll 1
    for (int rr = 0; rr < 8; rr++) {
        const int r = w * 8 + rr;
        float a = 0.f;
        #pragma unroll 4
        for (int ch = 0; ch < 16; ch++) {
            const int j = ch * 128 + lane * 4;
            const float4 hv = *(const float4*)(hF + j);
            const float4 wv = *(const float4*)(w1 + (size_t)r * 2048 + j);
            a = fmaf(wv.x, hv.x, fmaf(wv.y, hv.y,
                fmaf(wv.z, hv.z, fmaf(wv.w, hv.w, a))));
        }
        #pragma unroll
        for (int off = 16; off; off >>= 1) a += __shfl_xor_sync(0xffffffffu, a, off);
        if (lane == 0) sZ[r] = a + __ldg(b1 + r);
    }
    __syncthreads();
    if (w == 0) {
        float zv[4];
        #pragma unroll
        for (int qq = 0; qq < 4; qq++) zv[qq] = sZ[lane + 32 * qq];
        float s1 = zv[0] + zv[1] + zv[2] + zv[3];
        float s2 = zv[0] * zv[0] + zv[1] * zv[1] + zv[2] * zv[2] + zv[3] * zv[3];
        #pragma unroll
        for (int off = 16; off; off >>= 1) {
            s1 += __shfl_xor_sync(0xffffffffu, s1, off);
            s2 += __shfl_xor_sync(0xffffffffu, s2, off);
        }
        const float mu  = s1 * (1.f / 128.f);
        const float var = s2 * (1.f / 128.f) - mu * mu;
        const float rs  = __fdividef(1.f, sqrtf(var + 1e-5f));
        float o0 = 0.f, o1 = 0.f;
        #pragma unroll
        for (int qq = 0; qq < 4; qq++) {
            const int r = lane + 32 * qq;
            float zn = (zv[qq] - mu) * rs * __ldg(ln_g + r) + __ldg(ln_b + r);
            zn = fmaxf(zn, 0.f);
            o0 = fmaf(zn, __ldg(w2 + r), o0);
            o1 = fmaf(zn, __ldg(w2 + 128 + r), o1);
        }
        #pragma unroll
        for (int off = 16; off; off >>= 1) {
            o0 += __shfl_xor_sync(0xffffffffu, o0, off);
            o1 += __shfl_xor_sync(0xffffffffu, o1, off);
        }
        if (lane == 0) {
            out[b * 2 + 0] = o0 + __ldg(b2 + 0);
            out[b * 2 + 1] = o1 + __ldg(b2 + 1);
        }
    }
}

extern "C" void kernel_launch(void* const* d_in, const int* in_sizes, int n_in,
                              void* d_out, int out_size) {
    const int*   x      = (const int*)  d_in[0];
    const float* emb    = (const float*)d_in[1];
    const float* gate_w = (const float*)d_in[2];
    const float* gate_b = (const float*)d_in[3];
    const float* w1     = (const float*)d_in[4];
    const float* b1     = (const float*)d_in[5];
    const float* ln_g   = (const float*)d_in[6];
    const float* ln_b   = (const float*)d_in[7];
    const float* w2     = (const float*)d_in[8];
    const float* b2     = (const float*)d_in[9];
    const float* gp     = (const float*)d_in[10];
    float* out = (float*)d_out;

    setup_kernel<<<1, 256>>>(emb, gate_w, gate_b, gp);

    const int smem_bytes = SMEM_FLOATS * 4;
    cudaFuncSetAttribute(versor_main_kernel,
                         cudaFuncAttributeMaxDynamicSharedMemorySize, smem_bytes);
    versor_main_kernel<<<BB, NT, smem_bytes>>>(x, w1, b1, ln_g, ln_b, w2, b2, out);
}

// round 11
// speedup vs baseline: 1.9345x; 1.0453x over previous
#include <cuda_runtime.h>
#include <cuda_fp16.h>
#include <math.h>

#define BB 128
#define TT 512
#define GW_STRIDE 2080
#define NT 512

// gate row partition: [0,768) registers fp16, [768,1536) SMEM fp16, [1536,2048) L2/L1D stream
#define RROWS 768
#define SBASE 768
#define SROWS 768
#define XBASE 1536
#define HP 36                     // padded h row stride (floats)

// SMEM float offsets (sW16 = 768*64 halves = 24576 floats)
#define OFF_H  24576              // h state [64][36] fp32
#define OFF_HD 26880              // duplicated half2 h [2048]
#define OFF_A  28928              // 4x32x32 fp32
#define OFF_P  33024              // partials [16][68]
#define OFF_GR 34112              // 4x64
#define OFF_X  34368              // 512 ints
#define SMEM_FLOATS 34880         // 139520 bytes

__device__ float  d_A[4096];          // A[c][j][k]
__device__ float  d_gr[256];          // gate_b + r-term, [c][d]
__device__ __half d_gw16[2048 * 64];  // transposed fp16 weights [j][d]

static __device__ __forceinline__ unsigned long long pk2(float a, float b) {
    unsigned long long r; asm("mov.b64 %0, {%1,%2};" : "=l"(r) : "f"(a), "f"(b)); return r;
}
static __device__ __forceinline__ void ffma2(unsigned long long& d,
                                             unsigned long long a, unsigned long long b) {
    asm("fma.rn.f32x2 %0, %1, %2, %0;" : "+l"(d) : "l"(a), "l"(b));
}
static __device__ __forceinline__ float2 upk2(unsigned long long v) {
    float lo, hi; asm("mov.b64 {%0,%1}, %2;" : "=f"(lo), "=f"(hi) : "l"(v));
    return make_float2(lo, hi);
}
static __device__ __forceinline__ unsigned h2u(__half2 h) { return *(unsigned*)&h; }
static __device__ __forceinline__ __half2 u2h(unsigned u) { return *(__half2*)&u; }

__global__ void setup_kernel(const float* __restrict__ emb,
                             const float* __restrict__ gate_w,
                             const float* __restrict__ gate_b,
                             const float* __restrict__ gp) {
    __shared__ float r[4][32];
    int t = threadIdx.x;           // 256 threads
    if (t < 128) {
        int c = t >> 5, i = t & 31;
        float v = emb[c * 32 + i];
        float s = v * v;
        #pragma unroll
        for (int off = 16; off; off >>= 1) s += __shfl_xor_sync(0xffffffffu, s, off);
        r[c][i] = v / (sqrtf(s) + 1e-8f);
    }
    __syncthreads();
    for (int idx = t; idx < 4096; idx += 256) {
        int cc = idx >> 10, jk = idx & 1023;
        float acc = 0.f;
        #pragma unroll
        for (int ii = 0; ii < 32; ii++) acc += r[cc][ii] * gp[ii * 1024 + jk];
        d_A[idx] = acc;
    }
    for (int idx = t; idx < 256; idx += 256) {
        int cc = idx >> 6, d = idx & 63;
        float acc = gate_b[d];
        #pragma unroll
        for (int ii = 0; ii < 32; ii++)
            acc += gate_w[d * GW_STRIDE + 2048 + ii] * r[cc][ii];
        d_gr[idx] = acc;
    }
    for (int idx = t; idx < 2048 * 64; idx += 256) {
        int j = idx >> 6, d = idx & 63;
        d_gw16[idx] = __float2half_rn(gate_w[(size_t)d * GW_STRIDE + j]);
    }
}

__global__ void __launch_bounds__(NT, 1)
versor_main_kernel(const int* __restrict__ x,
                   const float* __restrict__ w1, const float* __restrict__ b1,
                   const float* __restrict__ ln_g, const float* __restrict__ ln_b,
                   const float* __restrict__ w2, const float* __restrict__ b2,
                   float* __restrict__ out) {
    extern __shared__ float sm[];
    __half*  sW16 = (__half*)sm;              // [768][64] fp16 (local row = j-768)
    float*   sH   = sm + OFF_H;               // h state [64][HP]
    __half2* sHd  = (__half2*)(sm + OFF_HD);  // duplicated (h,h), 2048 rows
    float*   sA   = sm + OFF_A;
    float*   sP   = sm + OFF_P;               // [16][68]
    float*   sGr  = sm + OFF_GR;
    int*     sX   = (int*)(sm + OFF_X);
    float*   sZ   = sP;                       // head alias

    const int tid  = threadIdx.x;
    const int lane = tid & 31;
    const int w    = tid >> 5;                // warp 0..15
    const int jway = lane >> 3;               // 0..3
    const int oct  = lane & 7;                // d-octet
    const int b    = blockIdx.x;
    const int grp  = w * 4 + jway;            // row group 0..63

    // ---- init SMEM ----
    for (int idx = tid; idx < SROWS * 8; idx += NT)   // 768*64 halves as uint4
        ((uint4*)sW16)[idx] = ((const uint4*)(d_gw16 + SBASE * 64))[idx];
    for (int idx = tid; idx < 4096; idx += NT) sA[idx] = d_A[idx];
    for (int idx = tid; idx < 256;  idx += NT) sGr[idx] = d_gr[idx];
    for (int idx = tid; idx < TT;   idx += NT) sX[idx] = x[b * TT + idx];
    for (int idx = tid; idx < 64 * HP; idx += NT)
        sH[idx] = ((idx % HP) == 0) ? 1.f : 0.f;
    for (int idx = tid; idx < 2048; idx += NT)
        sHd[idx] = __floats2half2_rn(((idx & 31) == 0) ? 1.f : 0.f,
                                     ((idx & 31) == 0) ? 1.f : 0.f);

    // ---- register fp16 weights: rows [0,768), 12 j x 8 d(4 half2)/thread ----
    unsigned wreg[48];
    {
        const int jb = grp * 12;
        #pragma unroll
        for (int jj = 0; jj < 12; jj++) {
            const uint4 v = *(const uint4*)(d_gw16 + (size_t)(jb + jj) * 64 + oct * 8);
            wreg[4 * jj + 0] = v.x; wreg[4 * jj + 1] = v.y;
            wreg[4 * jj + 2] = v.z; wreg[4 * jj + 3] = v.w;
        }
    }
    __syncthreads();

    const int dB = tid >> 3;              // phase-B versor (warp-exclusive row)
    const int s8 = tid & 7;               // 8-thread subgroup within versor
    const int k0 = s8 * 4;                // phase-B blade quad
    const __half2 hz = __float2half2_rn(0.f);

    #pragma unroll 1
    for (int t = 0; t < TT; t++) {
        const int c = sX[t];

        // ============ Phase A: gate partial dots (all HFMA2, octet-d) ============
        __half2 ha0 = hz, ha1 = hz, ha2 = hz, ha3 = hz;
        const int xb = XBASE + grp * 8;                  // streamed rows base

        uint4 xva0, xva1, xva2, xva3;
        {
            const uint4* g16 = (const uint4*)d_gw16;
            xva0 = __ldg(g16 + (xb + 0) * 8 + oct);
            xva1 = __ldg(g16 + (xb + 1) * 8 + oct);
            xva2 = __ldg(g16 + (xb + 2) * 8 + oct);
            xva3 = __ldg(g16 + (xb + 3) * 8 + oct);
        }
        // register rows (12), hj via 3 x LDS.128 on dup array
        {
            const int jb = grp * 12;
            #pragma unroll
            for (int q = 0; q < 3; q++) {
                const uint4 hq = *(const uint4*)(sHd + jb + 4 * q);
                const __half2 h0 = u2h(hq.x), h1 = u2h(hq.y);
                const __half2 h2 = u2h(hq.z), h3 = u2h(hq.w);
                ha0 = __hfma2(u2h(wreg[16 * q + 0]),  h0, ha0);
                ha1 = __hfma2(u2h(wreg[16 * q + 1]),  h0, ha1);
                ha2 = __hfma2(u2h(wreg[16 * q + 2]),  h0, ha2);
                ha3 = __hfma2(u2h(wreg[16 * q + 3]),  h0, ha3);
                ha0 = __hfma2(u2h(wreg[16 * q + 4]),  h1, ha0);
                ha1 = __hfma2(u2h(wreg[16 * q + 5]),  h1, ha1);
                ha2 = __hfma2(u2h(wreg[16 * q + 6]),  h1, ha2);
                ha3 = __hfma2(u2h(wreg[16 * q + 7]),  h1, ha3);
                ha0 = __hfma2(u2h(wreg[16 * q + 8]),  h2, ha0);
                ha1 = __hfma2(u2h(wreg[16 * q + 9]),  h2, ha1);
                ha2 = __hfma2(u2h(wreg[16 * q + 10]), h2, ha2);
                ha3 = __hfma2(u2h(wreg[16 * q + 11]), h2, ha3);
                ha0 = __hfma2(u2h(wreg[16 * q + 12]), h3, ha0);
                ha1 = __hfma2(u2h(wreg[16 * q + 13]), h3, ha1);
                ha2 = __hfma2(u2h(wreg[16 * q + 14]), h3, ha2);
                ha3 = __hfma2(u2h(wreg[16 * q + 15]), h3, ha3);
            }
        }
        // consume LDG batch A
        {
            const uint4 hq = *(const uint4*)(sHd + xb);
            const __half2 h0 = u2h(hq.x), h1 = u2h(hq.y);
            const __half2 h2 = u2h(hq.z), h3 = u2h(hq.w);
            ha0 = __hfma2(u2h(xva0.x), h0, ha0); ha1 = __hfma2(u2h(xva0.y), h0, ha1);
            ha2 = __hfma2(u2h(xva0.z), h0, ha2); ha3 = __hfma2(u2h(xva0.w), h0, ha3);
            ha0 = __hfma2(u2h(xva1.x), h1, ha0); ha1 = __hfma2(u2h(xva1.y), h1, ha1);
            ha2 = __hfma2(u2h(xva1.z), h1, ha2); ha3 = __hfma2(u2h(xva1.w), h1, ha3);
            ha0 = __hfma2(u2h(xva2.x), h2, ha0); ha1 = __hfma2(u2h(xva2.y), h2, ha1);
            ha2 = __hfma2(u2h(xva2.z), h2, ha2); ha3 = __hfma2(u2h(xva2.w), h2, ha3);
            ha0 = __hfma2(u2h(xva3.x), h3, ha0); ha1 = __hfma2(u2h(xva3.y), h3, ha1);
            ha2 = __hfma2(u2h(xva3.z), h3, ha2); ha3 = __hfma2(u2h(xva3.w), h3, ha3);
        }
        // issue LDG batch B
        {
            const uint4* g16 = (const uint4*)d_gw16;
            xva0 = __ldg(g16 + (xb + 4) * 8 + oct);
            xva1 = __ldg(g16 + (xb + 5) * 8 + oct);
            xva2 = __ldg(g16 + (xb + 6) * 8 + oct);
            xva3 = __ldg(g16 + (xb + 7) * 8 + oct);
        }
        // SMEM rows (12)
        {
            const int rb = grp * 12;           // local row in sW16
            #pragma unroll
            for (int q = 0; q < 3; q++) {
                const uint4 hq = *(const uint4*)(sHd + SBASE + rb + 4 * q);
                const __half2 hh[4] = { u2h(hq.x), u2h(hq.y), u2h(hq.z), u2h(hq.w) };
                #pragma unroll
                for (int rr = 0; rr < 4; rr++) {
                    const uint4 wv = ((const uint4*)sW16)[(rb + 4 * q + rr) * 8 + oct];
                    ha0 = __hfma2(u2h(wv.x), hh[rr], ha0);
                    ha1 = __hfma2(u2h(wv.y), hh[rr], ha1);
                    ha2 = __hfma2(u2h(wv.z), hh[rr], ha2);
                    ha3 = __hfma2(u2h(wv.w), hh[rr], ha3);
                }
            }
        }
        // consume LDG batch B
        {
            const uint4 hq = *(const uint4*)(sHd + xb + 4);
            const __half2 h0 = u2h(hq.x), h1 = u2h(hq.y);
            const __half2 h2 = u2h(hq.z), h3 = u2h(hq.w);
            ha0 = __hfma2(u2h(xva0.x), h0, ha0); ha1 = __hfma2(u2h(xva0.y), h0, ha1);
            ha2 = __hfma2(u2h(xva0.z), h0, ha2); ha3 = __hfma2(u2h(xva0.w), h0, ha3);
            ha0 = __hfma2(u2h(xva1.x), h1, ha0); ha1 = __hfma2(u2h(xva1.y), h1, ha1);
            ha2 = __hfma2(u2h(xva1.z), h1, ha2); ha3 = __hfma2(u2h(xva1.w), h1, ha3);
            ha0 = __hfma2(u2h(xva2.x), h2, ha0); ha1 = __hfma2(u2h(xva2.y), h2, ha1);
            ha2 = __hfma2(u2h(xva2.z), h2, ha2); ha3 = __hfma2(u2h(xva2.w), h2, ha3);
            ha0 = __hfma2(u2h(xva3.x), h3, ha0); ha1 = __hfma2(u2h(xva3.y), h3, ha1);
            ha2 = __hfma2(u2h(xva3.z), h3, ha2); ha3 = __hfma2(u2h(xva3.w), h3, ha3);
        }
        // reduce across the 4 jways, store fp32 partials
        {
            #pragma unroll
            for (int off = 8; off <= 16; off <<= 1) {
                ha0 = __hadd2(ha0, u2h(__shfl_xor_sync(0xffffffffu, h2u(ha0), off)));
                ha1 = __hadd2(ha1, u2h(__shfl_xor_sync(0xffffffffu, h2u(ha1), off)));
                ha2 = __hadd2(ha2, u2h(__shfl_xor_sync(0xffffffffu, h2u(ha2), off)));
                ha3 = __hadd2(ha3, u2h(__shfl_xor_sync(0xffffffffu, h2u(ha3), off)));
            }
            if (jway == 0) {
                const float2 f0 = __half22float2(ha0), f1 = __half22float2(ha1);
                const float2 f2 = __half22float2(ha2), f3 = __half22float2(ha3);
                *(float4*)(sP + w * 68 + oct * 8)     = make_float4(f0.x, f0.y, f1.x, f1.y);
                *(float4*)(sP + w * 68 + oct * 8 + 4) = make_float4(f2.x, f2.y, f3.x, f3.y);
            }
        }

        // ---- geometric product (pre-barrier; h stable, rows warp-exclusive) ----
        unsigned long long n0 = 0ull, n1 = 0ull;
        float4 hq4;
        {
            const float* hrow = sH + dB * HP;
            const ulonglong2* Ap = (const ulonglong2*)(sA + c * 1024) + s8;
            #pragma unroll
            for (int jq = 0; jq < 8; jq++) {
                const float4 hv = *(const float4*)(hrow + jq * 4);
                unsigned long long hp; ulonglong2 av;
                hp = pk2(hv.x, hv.x); av = Ap[(jq * 4 + 0) * 8];
                ffma2(n0, av.x, hp); ffma2(n1, av.y, hp);
                hp = pk2(hv.y, hv.y); av = Ap[(jq * 4 + 1) * 8];
                ffma2(n0, av.x, hp); ffma2(n1, av.y, hp);
                hp = pk2(hv.z, hv.z); av = Ap[(jq * 4 + 2) * 8];
                ffma2(n0, av.x, hp); ffma2(n1, av.y, hp);
                hp = pk2(hv.w, hv.w); av = Ap[(jq * 4 + 3) * 8];
                ffma2(n0, av.x, hp); ffma2(n1, av.y, hp);
            }
            hq4 = *(const float4*)(hrow + k0);
        }
        __syncthreads();   // barrier 1: partials visible; phase-A sHd reads done

        // ---- distributed gate reduce: 8 threads per versor ----
        float g;
        {
            float s = sP[(2 * s8) * 68 + dB] + sP[(2 * s8 + 1) * 68 + dB];
            s += __shfl_xor_sync(0xffffffffu, s, 1);
            s += __shfl_xor_sync(0xffffffffu, s, 2);
            s += __shfl_xor_sync(0xffffffffu, s, 4);
            s += sGr[c * 64 + dB];
            g = __fdividef(1.f, 1.f + __expf(-s));
        }

        // ---- blend + normalize + store (fp32 state + dup-half2) ----
        {
            const float om = 1.f - g;
            const float2 na = upk2(n0);
            const float2 nb = upk2(n1);
            float4 v;
            v.x = om * hq4.x + g * na.x;
            v.y = om * hq4.y + g * na.y;
            v.z = om * hq4.z + g * nb.x;
            v.w = om * hq4.w + g * nb.y;
            float ss = v.x * v.x + v.y * v.y + v.z * v.z + v.w * v.w;
            ss += __shfl_xor_sync(0xffffffffu, ss, 1);
            ss += __shfl_xor_sync(0xffffffffu, ss, 2);
            ss += __shfl_xor_sync(0xffffffffu, ss, 4);
            const float sc = __fdividef(1.f, sqrtf(ss) + 1e-8f);
            v.x *= sc; v.y *= sc; v.z *= sc; v.w *= sc;
            *(float4*)(sH + dB * HP + k0) = v;
            uint4 pd;
            pd.x = h2u(__floats2half2_rn(v.x, v.x));
            pd.y = h2u(__floats2half2_rn(v.y, v.y));
            pd.z = h2u(__floats2half2_rn(v.z, v.z));
            pd.w = h2u(__floats2half2_rn(v.w, v.w));
            *(uint4*)(sHd + dB * 32 + k0) = pd;
        }
        __syncthreads();   // barrier 2: new h (fp32 + dup) visible
    }

    // ============ Head: z = h@w1.T + b1, LN, relu, @w2.T + b2 ============
    #pragma unroll 1
    for (int rr = 0; rr < 8; rr++) {
        const int r = w * 8 + rr;
        float a = 0.f;
        #pragma unroll 4
        for (int ch = 0; ch < 16; ch++) {
            const int j = ch * 128 + lane * 4;
            const float4 hv = *(const float4*)(sH + (j >> 5) * HP + (j & 31));
            const float4 wv = *(const float4*)(w1 + (size_t)r * 2048 + j);
            a = fmaf(wv.x, hv.x, fmaf(wv.y, hv.y,
                fmaf(wv.z, hv.z, fmaf(wv.w, hv.w, a))));
        }
        #pragma unroll
        for (int off = 16; off; off >>= 1) a += __shfl_xor_sync(0xffffffffu, a, off);
        if (lane == 0) sZ[r] = a + __ldg(b1 + r);
    }
    __syncthreads();
    if (w == 0) {
        float zv[4];
        #pragma unroll
        for (int qq = 0; qq < 4; qq++) zv[qq] = sZ[lane + 32 * qq];
        float s1 = zv[0] + zv[1] + zv[2] + zv[3];
        float s2 = zv[0] * zv[0] + zv[1] * zv[1] + zv[2] * zv[2] + zv[3] * zv[3];
        #pragma unroll
        for (int off = 16; off; off >>= 1) {
            s1 += __shfl_xor_sync(0xffffffffu, s1, off);
            s2 += __shfl_xor_sync(0xffffffffu, s2, off);
        }
        const float mu  = s1 * (1.f / 128.f);
        const float var = s2 * (1.f / 128.f) - mu * mu;
        const float rs  = __fdividef(1.f, sqrtf(var + 1e-5f));
        float o0 = 0.f, o1 = 0.f;
        #pragma unroll
        for (int qq = 0; qq < 4; qq++) {
            const int r = lane + 32 * qq;
            float zn = (zv[qq] - mu) * rs * __ldg(ln_g + r) + __ldg(ln_b + r);
            zn = fmaxf(zn, 0.f);
            o0 = fmaf(zn, __ldg(w2 + r), o0);
            o1 = fmaf(zn, __ldg(w2 + 128 + r), o1);
        }
        #pragma unroll
        for (int off = 16; off; off >>= 1) {
            o0 += __shfl_xor_sync(0xffffffffu, o0, off);
            o1 += __shfl_xor_sync(0xffffffffu, o1, off);
        }
        if (lane == 0) {
            out[b * 2 + 0] = o0 + __ldg(b2 + 0);
            out[b * 2 + 1] = o1 + __ldg(b2 + 1);
        }
    }
}

extern "C" void kernel_launch(void* const* d_in, const int* in_sizes, int n_in,
                              void* d_out, int out_size) {
    const int*   x      = (const int*)  d_in[0];
    const float* emb    = (const float*)d_in[1];
    const float* gate_w = (const float*)d_in[2];
    const float* gate_b = (const float*)d_in[3];
    const float* w1     = (const float*)d_in[4];
    const float* b1     = (const float*)d_in[5];
    const float* ln_g   = (const float*)d_in[6];
    const float* ln_b   = (const float*)d_in[7];
    const float* w2     = (const float*)d_in[8];
    const float* b2     = (const float*)d_in[9];
    const float* gp     = (const float*)d_in[10];
    float* out = (float*)d_out;

    setup_kernel<<<1, 256>>>(emb, gate_w, gate_b, gp);

    const int smem_bytes = SMEM_FLOATS * 4;
    cudaFuncSetAttribute(versor_main_kernel,
                         cudaFuncAttributeMaxDynamicSharedMemorySize, smem_bytes);
    versor_main_kernel<<<BB, NT, smem_bytes>>>(x, w1, b1, ln_g, ln_b, w2, b2, out);
}

// round 12
// speedup vs baseline: 1.9470x; 1.0064x over previous
#include <cuda_runtime.h>
#include <cuda_fp16.h>
#include <math.h>

#define BB 128
#define TT 512
#define GW_STRIDE 2080
#define NT 512

// gate row partition: [0,768) registers fp16, [768,2048) SMEM fp16
#define RROWS 768
#define SBASE 768
#define SROWS 1280
#define HP 36                     // padded h row stride (floats)

// SMEM float offsets (sW16 = 1280*64 halves = 40960 floats)
#define OFF_H  40960              // h state [64][36] fp32
#define OFF_HD 43264              // duplicated half2 h [2048]
#define OFF_A  45312              // 4x32x32 fp32
#define OFF_P  49408              // partials [16][68]
#define OFF_GR 50496              // 4x64
#define OFF_X  50752              // 512 ints
#define SMEM_FLOATS 51264         // 205056 bytes

__device__ float  d_A[4096];          // A[c][j][k]
__device__ float  d_gr[256];          // gate_b + r-term, [c][d]
__device__ __half d_gw16[2048 * 64];  // transposed fp16 weights [j][d]

static __device__ __forceinline__ unsigned long long pk2(float a, float b) {
    unsigned long long r; asm("mov.b64 %0, {%1,%2};" : "=l"(r) : "f"(a), "f"(b)); return r;
}
static __device__ __forceinline__ void ffma2(unsigned long long& d,
                                             unsigned long long a, unsigned long long b) {
    asm("fma.rn.f32x2 %0, %1, %2, %0;" : "+l"(d) : "l"(a), "l"(b));
}
static __device__ __forceinline__ float2 upk2(unsigned long long v) {
    float lo, hi; asm("mov.b64 {%0,%1}, %2;" : "=f"(lo), "=f"(hi) : "l"(v));
    return make_float2(lo, hi);
}
static __device__ __forceinline__ unsigned h2u(__half2 h) { return *(unsigned*)&h; }
static __device__ __forceinline__ __half2 u2h(unsigned u) { return *(__half2*)&u; }

__global__ void setup_kernel(const float* __restrict__ emb,
                             const float* __restrict__ gate_w,
                             const float* __restrict__ gate_b,
                             const float* __restrict__ gp) {
    __shared__ float r[4][32];
    int t = threadIdx.x;           // 256 threads
    if (t < 128) {
        int c = t >> 5, i = t & 31;
        float v = emb[c * 32 + i];
        float s = v * v;
        #pragma unroll
        for (int off = 16; off; off >>= 1) s += __shfl_xor_sync(0xffffffffu, s, off);
        r[c][i] = v / (sqrtf(s) + 1e-8f);
    }
    __syncthreads();
    for (int idx = t; idx < 4096; idx += 256) {
        int cc = idx >> 10, jk = idx & 1023;
        float acc = 0.f;
        #pragma unroll
        for (int ii = 0; ii < 32; ii++) acc += r[cc][ii] * gp[ii * 1024 + jk];
        d_A[idx] = acc;
    }
    for (int idx = t; idx < 256; idx += 256) {
        int cc = idx >> 6, d = idx & 63;
        float acc = gate_b[d];
        #pragma unroll
        for (int ii = 0; ii < 32; ii++)
            acc += gate_w[d * GW_STRIDE + 2048 + ii] * r[cc][ii];
        d_gr[idx] = acc;
    }
    for (int idx = t; idx < 2048 * 64; idx += 256) {
        int j = idx >> 6, d = idx & 63;
        d_gw16[idx] = __float2half_rn(gate_w[(size_t)d * GW_STRIDE + j]);
    }
}

__global__ void __launch_bounds__(NT, 1)
versor_main_kernel(const int* __restrict__ x,
                   const float* __restrict__ w1, const float* __restrict__ b1,
                   const float* __restrict__ ln_g, const float* __restrict__ ln_b,
                   const float* __restrict__ w2, const float* __restrict__ b2,
                   float* __restrict__ out) {
    extern __shared__ float sm[];
    __half*  sW16 = (__half*)sm;              // [1280][64] fp16 (local row = j-768)
    float*   sH   = sm + OFF_H;               // h state [64][HP]
    __half2* sHd  = (__half2*)(sm + OFF_HD);  // duplicated (h,h), 2048 rows
    float*   sA   = sm + OFF_A;
    float*   sP   = sm + OFF_P;               // [16][68]
    float*   sGr  = sm + OFF_GR;
    int*     sX   = (int*)(sm + OFF_X);
    float*   sZ   = sP;                       // head alias

    const int tid  = threadIdx.x;
    const int lane = tid & 31;
    const int w    = tid >> 5;                // warp 0..15
    const int jway = lane >> 3;               // 0..3
    const int oct  = lane & 7;                // d-octet
    const int b    = blockIdx.x;
    const int grp  = w * 4 + jway;            // row group 0..63

    // ---- init SMEM ----
    for (int idx = tid; idx < SROWS * 8; idx += NT)   // 1280*64 halves as uint4
        ((uint4*)sW16)[idx] = ((const uint4*)(d_gw16 + SBASE * 64))[idx];
    for (int idx = tid; idx < 4096; idx += NT) sA[idx] = d_A[idx];
    for (int idx = tid; idx < 256;  idx += NT) sGr[idx] = d_gr[idx];
    for (int idx = tid; idx < TT;   idx += NT) sX[idx] = x[b * TT + idx];
    for (int idx = tid; idx < 64 * HP; idx += NT)
        sH[idx] = ((idx % HP) == 0) ? 1.f : 0.f;
    for (int idx = tid; idx < 2048; idx += NT)
        sHd[idx] = __floats2half2_rn(((idx & 31) == 0) ? 1.f : 0.f,
                                     ((idx & 31) == 0) ? 1.f : 0.f);

    // ---- register fp16 weights: rows [0,768), 12 j x 8 d(4 half2)/thread ----
    unsigned wreg[48];
    {
        const int jb = grp * 12;
        #pragma unroll
        for (int jj = 0; jj < 12; jj++) {
            const uint4 v = *(const uint4*)(d_gw16 + (size_t)(jb + jj) * 64 + oct * 8);
            wreg[4 * jj + 0] = v.x; wreg[4 * jj + 1] = v.y;
            wreg[4 * jj + 2] = v.z; wreg[4 * jj + 3] = v.w;
        }
    }
    __syncthreads();

    const int dB = tid >> 3;              // phase-B versor (warp-exclusive row)
    const int s8 = tid & 7;               // 8-thread subgroup within versor
    const int k0 = s8 * 4;                // phase-B blade quad
    const __half2 hz = __float2half2_rn(0.f);

    #pragma unroll 1
    for (int t = 0; t < TT; t++) {
        const int c = sX[t];

        // ============ Phase A: gate partial dots (all HFMA2, octet-d) ============
        __half2 ha0 = hz, ha1 = hz, ha2 = hz, ha3 = hz;
        // register rows (12), hj via 3 x LDS.128 on dup array
        {
            const int jb = grp * 12;
            #pragma unroll
            for (int q = 0; q < 3; q++) {
                const uint4 hq = *(const uint4*)(sHd + jb + 4 * q);
                const __half2 h0 = u2h(hq.x), h1 = u2h(hq.y);
                const __half2 h2 = u2h(hq.z), h3 = u2h(hq.w);
                ha0 = __hfma2(u2h(wreg[16 * q + 0]),  h0, ha0);
                ha1 = __hfma2(u2h(wreg[16 * q + 1]),  h0, ha1);
                ha2 = __hfma2(u2h(wreg[16 * q + 2]),  h0, ha2);
                ha3 = __hfma2(u2h(wreg[16 * q + 3]),  h0, ha3);
                ha0 = __hfma2(u2h(wreg[16 * q + 4]),  h1, ha0);
                ha1 = __hfma2(u2h(wreg[16 * q + 5]),  h1, ha1);
                ha2 = __hfma2(u2h(wreg[16 * q + 6]),  h1, ha2);
                ha3 = __hfma2(u2h(wreg[16 * q + 7]),  h1, ha3);
                ha0 = __hfma2(u2h(wreg[16 * q + 8]),  h2, ha0);
                ha1 = __hfma2(u2h(wreg[16 * q + 9]),  h2, ha1);
                ha2 = __hfma2(u2h(wreg[16 * q + 10]), h2, ha2);
                ha3 = __hfma2(u2h(wreg[16 * q + 11]), h2, ha3);
                ha0 = __hfma2(u2h(wreg[16 * q + 12]), h3, ha0);
                ha1 = __hfma2(u2h(wreg[16 * q + 13]), h3, ha1);
                ha2 = __hfma2(u2h(wreg[16 * q + 14]), h3, ha2);
                ha3 = __hfma2(u2h(wreg[16 * q + 15]), h3, ha3);
            }
        }
        // SMEM rows (20): local rows [grp*20, grp*20+20)
        {
            const int rb = grp * 20;
            #pragma unroll
            for (int q = 0; q < 5; q++) {
                const uint4 hq = *(const uint4*)(sHd + SBASE + rb + 4 * q);
                const __half2 hh[4] = { u2h(hq.x), u2h(hq.y), u2h(hq.z), u2h(hq.w) };
                #pragma unroll
                for (int rr = 0; rr < 4; rr++) {
                    const uint4 wv = ((const uint4*)sW16)[(rb + 4 * q + rr) * 8 + oct];
                    ha0 = __hfma2(u2h(wv.x), hh[rr], ha0);
                    ha1 = __hfma2(u2h(wv.y), hh[rr], ha1);
                    ha2 = __hfma2(u2h(wv.z), hh[rr], ha2);
                    ha3 = __hfma2(u2h(wv.w), hh[rr], ha3);
                }
            }
        }
        // reduce across the 4 jways, store fp32 partials
        {
            #pragma unroll
            for (int off = 8; off <= 16; off <<= 1) {
                ha0 = __hadd2(ha0, u2h(__shfl_xor_sync(0xffffffffu, h2u(ha0), off)));
                ha1 = __hadd2(ha1, u2h(__shfl_xor_sync(0xffffffffu, h2u(ha1), off)));
                ha2 = __hadd2(ha2, u2h(__shfl_xor_sync(0xffffffffu, h2u(ha2), off)));
                ha3 = __hadd2(ha3, u2h(__shfl_xor_sync(0xffffffffu, h2u(ha3), off)));
            }
            if (jway == 0) {
                const float2 f0 = __half22float2(ha0), f1 = __half22float2(ha1);
                const float2 f2 = __half22float2(ha2), f3 = __half22float2(ha3);
                *(float4*)(sP + w * 68 + oct * 8)     = make_float4(f0.x, f0.y, f1.x, f1.y);
                *(float4*)(sP + w * 68 + oct * 8 + 4) = make_float4(f2.x, f2.y, f3.x, f3.y);
            }
        }

        // ---- geometric product (pre-barrier; h stable, rows warp-exclusive) ----
        unsigned long long n0 = 0ull, n1 = 0ull;
        float4 hq4;
        {
            const float* hrow = sH + dB * HP;
            const ulonglong2* Ap = (const ulonglong2*)(sA + c * 1024) + s8;
            #pragma unroll
            for (int jq = 0; jq < 8; jq++) {
                const float4 hv = *(const float4*)(hrow + jq * 4);
                unsigned long long hp; ulonglong2 av;
                hp = pk2(hv.x, hv.x); av = Ap[(jq * 4 + 0) * 8];
                ffma2(n0, av.x, hp); ffma2(n1, av.y, hp);
                hp = pk2(hv.y, hv.y); av = Ap[(jq * 4 + 1) * 8];
                ffma2(n0, av.x, hp); ffma2(n1, av.y, hp);
                hp = pk2(hv.z, hv.z); av = Ap[(jq * 4 + 2) * 8];
                ffma2(n0, av.x, hp); ffma2(n1, av.y, hp);
                hp = pk2(hv.w, hv.w); av = Ap[(jq * 4 + 3) * 8];
                ffma2(n0, av.x, hp); ffma2(n1, av.y, hp);
            }
            hq4 = *(const float4*)(hrow + k0);
        }
        __syncthreads();   // barrier 1: partials visible; phase-A sHd reads done

        // ---- distributed gate reduce: 8 threads per versor ----
        float g;
        {
            float s = sP[(2 * s8) * 68 + dB] + sP[(2 * s8 + 1) * 68 + dB];
            s += __shfl_xor_sync(0xffffffffu, s, 1);
            s += __shfl_xor_sync(0xffffffffu, s, 2);
            s += __shfl_xor_sync(0xffffffffu, s, 4);
            s += sGr[c * 64 + dB];
            g = __fdividef(1.f, 1.f + __expf(-s));
        }

        // ---- blend + normalize + store (fp32 state + dup-half2) ----
        {
            const float om = 1.f - g;
            const float2 na = upk2(n0);
            const float2 nb = upk2(n1);
            float4 v;
            v.x = om * hq4.x + g * na.x;
            v.y = om * hq4.y + g * na.y;
            v.z = om * hq4.z + g * nb.x;
            v.w = om * hq4.w + g * nb.y;
            float ss = v.x * v.x + v.y * v.y + v.z * v.z + v.w * v.w;
            ss += __shfl_xor_sync(0xffffffffu, ss, 1);
            ss += __shfl_xor_sync(0xffffffffu, ss, 2);
            ss += __shfl_xor_sync(0xffffffffu, ss, 4);
            const float sc = __fdividef(1.f, sqrtf(ss) + 1e-8f);
            v.x *= sc; v.y *= sc; v.z *= sc; v.w *= sc;
            *(float4*)(sH + dB * HP + k0) = v;
            uint4 pd;
            pd.x = h2u(__floats2half2_rn(v.x, v.x));
            pd.y = h2u(__floats2half2_rn(v.y, v.y));
            pd.z = h2u(__floats2half2_rn(v.z, v.z));
            pd.w = h2u(__floats2half2_rn(v.w, v.w));
            *(uint4*)(sHd + dB * 32 + k0) = pd;
        }
        __syncthreads();   // barrier 2: new h (fp32 + dup) visible
    }

    // ============ Head: z = h@w1.T + b1, LN, relu, @w2.T + b2 ============
    #pragma unroll 1
    for (int rr = 0; rr < 8; rr++) {
        const int r = w * 8 + rr;
        float a = 0.f;
        #pragma unroll 4
        for (int ch = 0; ch < 16; ch++) {
            const int j = ch * 128 + lane * 4;
            const float4 hv = *(const float4*)(sH + (j >> 5) * HP + (j & 31));
            const float4 wv = *(const float4*)(w1 + (size_t)r * 2048 + j);
            a = fmaf(wv.x, hv.x, fmaf(wv.y, hv.y,
                fmaf(wv.z, hv.z, fmaf(wv.w, hv.w, a))));
        }
        #pragma unroll
        for (int off = 16; off; off >>= 1) a += __shfl_xor_sync(0xffffffffu, a, off);
        if (lane == 0) sZ[r] = a + __ldg(b1 + r);
    }
    __syncthreads();
    if (w == 0) {
        float zv[4];
        #pragma unroll
        for (int qq = 0; qq < 4; qq++) zv[qq] = sZ[lane + 32 * qq];
        float s1 = zv[0] + zv[1] + zv[2] + zv[3];
        float s2 = zv[0] * zv[0] + zv[1] * zv[1] + zv[2] * zv[2] + zv[3] * zv[3];
        #pragma unroll
        for (int off = 16; off; off >>= 1) {
            s1 += __shfl_xor_sync(0xffffffffu, s1, off);
            s2 += __shfl_xor_sync(0xffffffffu, s2, off);
        }
        const float mu  = s1 * (1.f / 128.f);
        const float var = s2 * (1.f / 128.f) - mu * mu;
        const float rs  = __fdividef(1.f, sqrtf(var + 1e-5f));
        float o0 = 0.f, o1 = 0.f;
        #pragma unroll
        for (int qq = 0; qq < 4; qq++) {
            const int r = lane + 32 * qq;
            float zn = (zv[qq] - mu) * rs * __ldg(ln_g + r) + __ldg(ln_b + r);
            zn = fmaxf(zn, 0.f);
            o0 = fmaf(zn, __ldg(w2 + r), o0);
            o1 = fmaf(zn, __ldg(w2 + 128 + r), o1);
        }
        #pragma unroll
        for (int off = 16; off; off >>= 1) {
            o0 += __shfl_xor_sync(0xffffffffu, o0, off);
            o1 += __shfl_xor_sync(0xffffffffu, o1, off);
        }
        if (lane == 0) {
            out[b * 2 + 0] = o0 + __ldg(b2 + 0);
            out[b * 2 + 1] = o1 + __ldg(b2 + 1);
        }
    }
}

extern "C" void kernel_launch(void* const* d_in, const int* in_sizes, int n_in,
                              void* d_out, int out_size) {
    const int*   x      = (const int*)  d_in[0];
    const float* emb    = (const float*)d_in[1];
    const float* gate_w = (const float*)d_in[2];
    const float* gate_b = (const float*)d_in[3];
    const float* w1     = (const float*)d_in[4];
    const float* b1     = (const float*)d_in[5];
    const float* ln_g   = (const float*)d_in[6];
    const float* ln_b   = (const float*)d_in[7];
    const float* w2     = (const float*)d_in[8];
    const float* b2     = (const float*)d_in[9];
    const float* gp     = (const float*)d_in[10];
    float* out = (float*)d_out;

    setup_kernel<<<1, 256>>>(emb, gate_w, gate_b, gp);

    const int smem_bytes = SMEM_FLOATS * 4;
    cudaFuncSetAttribute(versor_main_kernel,
                         cudaFuncAttributeMaxDynamicSharedMemorySize, smem_bytes);
    versor_main_kernel<<<BB, NT, smem_bytes>>>(x, w1, b1, ln_g, ln_b, w2, b2, out);
}